// round 2
// baseline (speedup 1.0000x reference)
#include <cuda_runtime.h>
#include <math.h>

// Problem constants
#define B_  16
#define C_  48
#define H_  64
#define W_  64
#define HW_ 4096          // H_*W_
#define NC_ 2048          // N_CORR
#define TQ  64            // query tile
#define TM  64            // db tile

// Scratch (no cudaMalloc allowed)
__device__ float g_norm1[B_ * C_ * HW_];   // normalized x1, (b, c, m) layout
__device__ float g_norm2[B_ * C_ * HW_];   // normalized x2
__device__ float g_maxdot[2 * B_ * NC_];   // [dir][b][n]
__device__ float g_loss[B_];

// ---------------------------------------------------------------------------
// Kernel 1: per-pixel L2 normalize over channels, keep (C, HW) layout.
// grid: (B_*HW_/256, 2), block 256. blockIdx.y selects tensor.
// ---------------------------------------------------------------------------
__global__ void normalize_kernel(const float* __restrict__ x1,
                                 const float* __restrict__ x2) {
    int t = blockIdx.x * blockDim.x + threadIdx.x;     // 0 .. B_*HW_-1
    const float* src = blockIdx.y ? x2 : x1;
    float*       dst = blockIdx.y ? g_norm2 : g_norm1;
    int b = t >> 12;
    int m = t & (HW_ - 1);
    const float* p = src + (size_t)b * C_ * HW_ + m;
    float v[C_];
    float ss = 0.f;
#pragma unroll
    for (int c = 0; c < C_; ++c) {
        v[c] = p[c * HW_];
        ss = fmaf(v[c], v[c], ss);
    }
    float inv = 1.0f / fmaxf(sqrtf(ss), 1e-12f);
    float* q = dst + (size_t)b * C_ * HW_ + m;
#pragma unroll
    for (int c = 0; c < C_; ++c) q[c * HW_] = v[c] * inv;
}

// ---------------------------------------------------------------------------
// Kernel 2: masked max-dot. grid: (NC_/TQ, B_, 2), block 256 (16x16).
// dir 0: queries = norm1 at ids, db = norm2, mask center = fp2
// dir 1: queries = norm2 at fp2lin, db = norm1, mask center = pos(ids)
// ---------------------------------------------------------------------------
__global__ __launch_bounds__(256, 4)
void maxdot_kernel(const int* __restrict__ ids,
                   const int* __restrict__ fp2) {
    __shared__ __align__(16) float Qs[C_][TQ];   // [k][q]
    __shared__ __align__(16) float Ms[C_][TM];   // [k][m]
    __shared__ int s_qi[TQ];
    __shared__ int s_ci[TQ];
    __shared__ int s_cj[TQ];

    const int tid  = threadIdx.x;
    const int b    = blockIdx.y;
    const int dir  = blockIdx.z;
    const int nbas = blockIdx.x * TQ;

    // query indices + mask centers
    if (tid < TQ) {
        int n  = nbas + tid;
        int id = ids[b * NC_ + n];
        int fi = fp2[(b * 2 + 0) * NC_ + n];
        int fj = fp2[(b * 2 + 1) * NC_ + n];
        if (dir == 0) { s_qi[tid] = id;            s_ci[tid] = fi;      s_cj[tid] = fj; }
        else          { s_qi[tid] = fi * W_ + fj;  s_ci[tid] = id >> 6; s_cj[tid] = id & 63; }
    }
    const float* qf  = (dir == 0) ? (g_norm1 + (size_t)b * C_ * HW_)
                                  : (g_norm2 + (size_t)b * C_ * HW_);
    const float* dbf = (dir == 0) ? (g_norm2 + (size_t)b * C_ * HW_)
                                  : (g_norm1 + (size_t)b * C_ * HW_);
    __syncthreads();

    // gather query tile into [k][q] smem
    for (int idx = tid; idx < C_ * TQ; idx += 256) {
        int q = idx & (TQ - 1);
        int c = idx >> 6;
        Qs[c][q] = qf[c * HW_ + s_qi[q]];
    }

    const int tx = tid & 15;   // m dimension (4 each)
    const int ty = tid >> 4;   // q dimension (4 each)

    int ci[4], cj[4];
#pragma unroll
    for (int i = 0; i < 4; ++i) { ci[i] = s_ci[ty * 4 + i]; cj[i] = s_cj[ty * 4 + i]; }

    float rmax[4] = {-1e30f, -1e30f, -1e30f, -1e30f};
    __syncthreads();   // Qs ready

    for (int mt = 0; mt < HW_; mt += TM) {
        // load db tile: (C_, TM) directly from channel-major global -> [k][m]
        for (int idx = tid; idx < C_ * (TM / 4); idx += 256) {
            int c = idx >> 4;
            int g = idx & 15;
            float4 v = *(const float4*)(dbf + c * HW_ + mt + g * 4);
            *(float4*)&Ms[c][g * 4] = v;
        }
        __syncthreads();

        float acc[4][4];
#pragma unroll
        for (int i = 0; i < 4; ++i)
#pragma unroll
            for (int j = 0; j < 4; ++j) acc[i][j] = 0.f;

#pragma unroll
        for (int k = 0; k < C_; ++k) {
            float4 aq = *(const float4*)&Qs[k][ty * 4];
            float4 bm = *(const float4*)&Ms[k][tx * 4];
            float a[4] = {aq.x, aq.y, aq.z, aq.w};
            float bb[4] = {bm.x, bm.y, bm.z, bm.w};
#pragma unroll
            for (int i = 0; i < 4; ++i)
#pragma unroll
                for (int j = 0; j < 4; ++j)
                    acc[i][j] = fmaf(a[i], bb[j], acc[i][j]);
        }

        // mask + running max
#pragma unroll
        for (int j = 0; j < 4; ++j) {
            int m  = mt + tx * 4 + j;
            int mi = m >> 6;
            int mj = m & 63;
#pragma unroll
            for (int i = 0; i < 4; ++i) {
                bool excl = (abs(mi - ci[i]) <= 4) && (abs(mj - cj[i]) <= 4);
                float v = excl ? -1e30f : acc[i][j];
                rmax[i] = fmaxf(rmax[i], v);
            }
        }
        __syncthreads();
    }

    // reduce over the 16 tx-threads sharing each q row.
    // lane = (ty&1)*16 + tx, so xor 8/4/2/1 stays within the 16-lane group.
#pragma unroll
    for (int i = 0; i < 4; ++i) {
        float v = rmax[i];
        v = fmaxf(v, __shfl_xor_sync(0xffffffffu, v, 8));
        v = fmaxf(v, __shfl_xor_sync(0xffffffffu, v, 4));
        v = fmaxf(v, __shfl_xor_sync(0xffffffffu, v, 2));
        v = fmaxf(v, __shfl_xor_sync(0xffffffffu, v, 1));
        if (tx == 0)
            g_maxdot[(dir * B_ + b) * NC_ + nbas + ty * 4 + i] = v;
    }
}

// ---------------------------------------------------------------------------
// Kernel 3: per-image weighted loss. grid: B_, block 256.
// ---------------------------------------------------------------------------
__global__ void loss_kernel(const float* __restrict__ att1,
                            const float* __restrict__ att2,
                            const int* __restrict__ ids,
                            const int* __restrict__ fp2) {
    __shared__ float s_t[256];
    __shared__ float s_w[256];
    int b   = blockIdx.x;
    int tid = threadIdx.x;
    float st = 0.f, sw = 0.f;
    const float* n1 = g_norm1 + (size_t)b * C_ * HW_;
    const float* n2 = g_norm2 + (size_t)b * C_ * HW_;
    for (int n = tid; n < NC_; n += 256) {
        int id  = ids[b * NC_ + n];
        int fi  = fp2[(b * 2 + 0) * NC_ + n];
        int fj  = fp2[(b * 2 + 1) * NC_ + n];
        int lin = fi * W_ + fj;
        float dot = 0.f;
#pragma unroll
        for (int c = 0; c < C_; ++c)
            dot = fmaf(n1[c * HW_ + id], n2[c * HW_ + lin], dot);
        float mx = fmaxf(g_maxdot[b * NC_ + n],
                         g_maxdot[B_ * NC_ + b * NC_ + n]);
        // diff = (2-2dot) - (2-2mx) = 2*(mx - dot); loss term = relu(1 + diff)
        float term = fmaxf(1.0f + 2.0f * (mx - dot), 0.0f);
        float w = att1[b * HW_ + id] * att2[b * HW_ + lin];
        st = fmaf(w, term, st);
        sw += w;
    }
    s_t[tid] = st; s_w[tid] = sw;
    __syncthreads();
    for (int s = 128; s > 0; s >>= 1) {
        if (tid < s) { s_t[tid] += s_t[tid + s]; s_w[tid] += s_w[tid + s]; }
        __syncthreads();
    }
    if (tid == 0) g_loss[b] = s_t[0] / s_w[0];
}

// ---------------------------------------------------------------------------
// Kernel 4: mean over batch -> d_out[0]
// ---------------------------------------------------------------------------
__global__ void mean_kernel(float* __restrict__ out) {
    if (threadIdx.x == 0) {
        float s = 0.f;
#pragma unroll
        for (int b = 0; b < B_; ++b) s += g_loss[b];
        out[0] = s / (float)B_;
    }
}

// ---------------------------------------------------------------------------
extern "C" void kernel_launch(void* const* d_in, const int* in_sizes, int n_in,
                              void* d_out, int out_size) {
    const float* x1   = (const float*)d_in[0];
    const float* x2   = (const float*)d_in[1];
    const float* att1 = (const float*)d_in[2];
    const float* att2 = (const float*)d_in[3];
    const int*   ids  = (const int*)d_in[4];
    const int*   fp2  = (const int*)d_in[5];
    float* out = (float*)d_out;

    dim3 gN(B_ * HW_ / 256, 2);
    normalize_kernel<<<gN, 256>>>(x1, x2);

    dim3 gM(NC_ / TQ, B_, 2);
    maxdot_kernel<<<gM, 256>>>(ids, fp2);

    loss_kernel<<<B_, 256>>>(att1, att2, ids, fp2);
    mean_kernel<<<1, 32>>>(out);
}

// round 4
// speedup vs baseline: 1.0274x; 1.0274x over previous
#include <cuda_runtime.h>
#include <math.h>

// Problem constants
#define B_  16
#define C_  48
#define H_  64
#define W_  64
#define HW_ 4096          // H_*W_
#define NC_ 2048          // N_CORR
#define TQ  64            // query tile
#define TM  64            // db tile (one grid row exactly)

typedef unsigned long long u64t;

// Scratch (no cudaMalloc allowed)
__device__ float g_norm1[B_ * C_ * HW_];   // normalized x1, (b, c, m) layout
__device__ float g_norm2[B_ * C_ * HW_];   // normalized x2
__device__ float g_maxdot[2 * B_ * NC_];   // [dir][b][n]
__device__ float g_loss[B_];

__device__ __forceinline__ void fma2(u64t& d, u64t a, u64t b) {
    asm("fma.rn.f32x2 %0, %1, %2, %0;" : "+l"(d) : "l"(a), "l"(b));
}

// ---------------------------------------------------------------------------
// Kernel 1: per-pixel L2 normalize over channels, keep (C, HW) layout.
// ---------------------------------------------------------------------------
__global__ void normalize_kernel(const float* __restrict__ x1,
                                 const float* __restrict__ x2) {
    int t = blockIdx.x * blockDim.x + threadIdx.x;     // 0 .. B_*HW_-1
    const float* src = blockIdx.y ? x2 : x1;
    float*       dst = blockIdx.y ? g_norm2 : g_norm1;
    int b = t >> 12;
    int m = t & (HW_ - 1);
    const float* p = src + (size_t)b * C_ * HW_ + m;
    float v[C_];
    float ss = 0.f;
#pragma unroll
    for (int c = 0; c < C_; ++c) {
        v[c] = p[c * HW_];
        ss = fmaf(v[c], v[c], ss);
    }
    float inv = 1.0f / fmaxf(sqrtf(ss), 1e-12f);
    float* q = dst + (size_t)b * C_ * HW_ + m;
#pragma unroll
    for (int c = 0; c < C_; ++c) q[c * HW_] = v[c] * inv;
}

// ---------------------------------------------------------------------------
// Kernel 2: masked max-dot via packed f32x2 FMA.
// grid: (NC_/TQ, B_, 2), block 256 (16x16), thread tile 4q x 4m.
// Query tile stored DUPLICATED ({v,v}) in smem so the broadcast operand of
// fma.rn.f32x2 needs no packing ALU; db m-pairs are naturally adjacent.
// TM=64 => each tile is exactly one grid row => 1 row-check per query.
// ---------------------------------------------------------------------------
__global__ __launch_bounds__(256, 4)
void maxdot_kernel(const int* __restrict__ ids,
                   const int* __restrict__ fp2) {
    __shared__ __align__(16) float2 Qs2[C_][TQ];   // [k][q] duplicated
    __shared__ __align__(16) float  Ms[C_][TM];    // [k][m]
    __shared__ int s_qi[TQ];
    __shared__ int s_ci[TQ];
    __shared__ int s_cj[TQ];

    const int tid  = threadIdx.x;
    const int b    = blockIdx.y;
    const int dir  = blockIdx.z;
    const int nbas = blockIdx.x * TQ;

    if (tid < TQ) {
        int n  = nbas + tid;
        int id = ids[b * NC_ + n];
        int fi = fp2[(b * 2 + 0) * NC_ + n];
        int fj = fp2[(b * 2 + 1) * NC_ + n];
        if (dir == 0) { s_qi[tid] = id;            s_ci[tid] = fi;      s_cj[tid] = fj; }
        else          { s_qi[tid] = fi * W_ + fj;  s_ci[tid] = id >> 6; s_cj[tid] = id & 63; }
    }
    const float* qf  = (dir == 0) ? (g_norm1 + (size_t)b * C_ * HW_)
                                  : (g_norm2 + (size_t)b * C_ * HW_);
    const float* dbf = (dir == 0) ? (g_norm2 + (size_t)b * C_ * HW_)
                                  : (g_norm1 + (size_t)b * C_ * HW_);
    __syncthreads();

    // gather query tile, duplicated
    for (int idx = tid; idx < C_ * TQ; idx += 256) {
        int q = idx & (TQ - 1);
        int c = idx >> 6;
        float v = qf[c * HW_ + s_qi[q]];
        Qs2[c][q] = make_float2(v, v);
    }

    const int tx = tid & 15;   // m dimension: cols tx*4 .. tx*4+3
    const int ty = tid >> 4;   // q dimension: rows ty*4 .. ty*4+3

    int ci[4];
    bool colbad[4][4];         // |(tx*4+cc) - cj[i]| <= 4, tile-independent
#pragma unroll
    for (int i = 0; i < 4; ++i) {
        ci[i] = s_ci[ty * 4 + i];
        int cjv = s_cj[ty * 4 + i];
#pragma unroll
        for (int cc = 0; cc < 4; ++cc)
            colbad[i][cc] = ((unsigned)(tx * 4 + cc - cjv + 4)) <= 8u;
    }

    float rmax[4] = {-1e30f, -1e30f, -1e30f, -1e30f};
    __syncthreads();   // Qs2 ready

    for (int mt = 0; mt < HW_; mt += TM) {
        // db tile: (C_, TM) from channel-major global -> [k][m]
        for (int idx = tid; idx < C_ * (TM / 4); idx += 256) {
            int c = idx >> 4;
            int g = idx & 15;
            float4 v = *(const float4*)(dbf + c * HW_ + mt + g * 4);
            *(float4*)&Ms[c][g * 4] = v;
        }
        __syncthreads();

        u64t acc[4][2];
#pragma unroll
        for (int i = 0; i < 4; ++i) { acc[i][0] = 0ull; acc[i][1] = 0ull; }

#pragma unroll
        for (int k = 0; k < C_; ++k) {
            ulonglong2 q0 = *(const ulonglong2*)&Qs2[k][ty * 4];      // {q0q0,q1q1}
            ulonglong2 q1 = *(const ulonglong2*)&Qs2[k][ty * 4 + 2];  // {q2q2,q3q3}
            ulonglong2 bv = *(const ulonglong2*)&Ms[k][tx * 4];       // {m0m1,m2m3}
            fma2(acc[0][0], q0.x, bv.x);  fma2(acc[0][1], q0.x, bv.y);
            fma2(acc[1][0], q0.y, bv.x);  fma2(acc[1][1], q0.y, bv.y);
            fma2(acc[2][0], q1.x, bv.x);  fma2(acc[2][1], q1.x, bv.y);
            fma2(acc[3][0], q1.y, bv.x);  fma2(acc[3][1], q1.y, bv.y);
        }

        // mask + running max. Whole tile is grid row rA.
        int rA = mt >> 6;
#pragma unroll
        for (int i = 0; i < 4; ++i) {
            bool rowin = ((unsigned)(rA - ci[i] + 4)) <= 8u;
#pragma unroll
            for (int j = 0; j < 2; ++j) {
                float2 p = *(float2*)&acc[i][j];
                float v0 = (rowin && colbad[i][j * 2 + 0]) ? -1e30f : p.x;
                float v1 = (rowin && colbad[i][j * 2 + 1]) ? -1e30f : p.y;
                rmax[i] = fmaxf(rmax[i], fmaxf(v0, v1));
            }
        }
        __syncthreads();
    }

    // reduce over the 16 tx-threads sharing each q row.
#pragma unroll
    for (int i = 0; i < 4; ++i) {
        float v = rmax[i];
        v = fmaxf(v, __shfl_xor_sync(0xffffffffu, v, 8));
        v = fmaxf(v, __shfl_xor_sync(0xffffffffu, v, 4));
        v = fmaxf(v, __shfl_xor_sync(0xffffffffu, v, 2));
        v = fmaxf(v, __shfl_xor_sync(0xffffffffu, v, 1));
        if (tx == 0)
            g_maxdot[(dir * B_ + b) * NC_ + nbas + ty * 4 + i] = v;
    }
}

// ---------------------------------------------------------------------------
// Kernel 3: per-image weighted loss. grid: B_, block 256.
// ---------------------------------------------------------------------------
__global__ void loss_kernel(const float* __restrict__ att1,
                            const float* __restrict__ att2,
                            const int* __restrict__ ids,
                            const int* __restrict__ fp2) {
    __shared__ float s_t[256];
    __shared__ float s_w[256];
    int b   = blockIdx.x;
    int tid = threadIdx.x;
    float st = 0.f, sw = 0.f;
    const float* n1 = g_norm1 + (size_t)b * C_ * HW_;
    const float* n2 = g_norm2 + (size_t)b * C_ * HW_;
    for (int n = tid; n < NC_; n += 256) {
        int id  = ids[b * NC_ + n];
        int fi  = fp2[(b * 2 + 0) * NC_ + n];
        int fj  = fp2[(b * 2 + 1) * NC_ + n];
        int lin = fi * W_ + fj;
        float dot = 0.f;
#pragma unroll
        for (int c = 0; c < C_; ++c)
            dot = fmaf(n1[c * HW_ + id], n2[c * HW_ + lin], dot);
        float mx = fmaxf(g_maxdot[b * NC_ + n],
                         g_maxdot[B_ * NC_ + b * NC_ + n]);
        // diff = (2-2dot) - (2-2mx) = 2*(mx - dot); loss term = relu(1 + diff)
        float term = fmaxf(1.0f + 2.0f * (mx - dot), 0.0f);
        float w = att1[b * HW_ + id] * att2[b * HW_ + lin];
        st = fmaf(w, term, st);
        sw += w;
    }
    s_t[tid] = st; s_w[tid] = sw;
    __syncthreads();
    for (int s = 128; s > 0; s >>= 1) {
        if (tid < s) { s_t[tid] += s_t[tid + s]; s_w[tid] += s_w[tid + s]; }
        __syncthreads();
    }
    if (tid == 0) g_loss[b] = s_t[0] / s_w[0];
}

// ---------------------------------------------------------------------------
// Kernel 4: mean over batch -> d_out[0]
// ---------------------------------------------------------------------------
__global__ void mean_kernel(float* __restrict__ out) {
    if (threadIdx.x == 0) {
        float s = 0.f;
#pragma unroll
        for (int b = 0; b < B_; ++b) s += g_loss[b];
        out[0] = s / (float)B_;
    }
}

// ---------------------------------------------------------------------------
extern "C" void kernel_launch(void* const* d_in, const int* in_sizes, int n_in,
                              void* d_out, int out_size) {
    const float* x1   = (const float*)d_in[0];
    const float* x2   = (const float*)d_in[1];
    const float* att1 = (const float*)d_in[2];
    const float* att2 = (const float*)d_in[3];
    const int*   ids  = (const int*)d_in[4];
    const int*   fp2  = (const int*)d_in[5];
    float* out = (float*)d_out;

    dim3 gN(B_ * HW_ / 256, 2);
    normalize_kernel<<<gN, 256>>>(x1, x2);

    dim3 gM(NC_ / TQ, B_, 2);
    maxdot_kernel<<<gM, 256>>>(ids, fp2);

    loss_kernel<<<B_, 256>>>(att1, att2, ids, fp2);
    mean_kernel<<<1, 32>>>(out);
}

// round 7
// speedup vs baseline: 6.0315x; 5.8705x over previous
#include <cuda_runtime.h>
#include <cuda_fp16.h>
#include <math.h>

#define B_   16
#define W_   64
#define HW_  4096
#define NC_  2048
#define CC_  48

typedef unsigned int u32;
typedef unsigned long long u64;

// ---------------- scratch (__device__ globals; no allocation) ----------------
__device__ __half g_D[2][B_][HW_][CC_];   // [0]=norm(x2), [1]=norm(x1); packed 96B rows
__device__ __half g_Q[2][B_][NC_][CC_];   // gathered queries per dir
__device__ int    g_ctr[2 * B_ * NC_];    // (ci<<8)|cj exclusion centers
__device__ float  g_maxdot[2 * B_ * NC_];
__device__ float  g_loss[B_];

// ---------------- PTX helpers (portable, no sm_103a-gated features) ---------
__device__ __forceinline__ u32 s2u(const void* p) {
    u32 a;
    asm("{ .reg .u64 t; cvta.to.shared.u64 t, %1; cvt.u32.u64 %0, t; }" : "=r"(a) : "l"(p));
    return a;
}
__device__ __forceinline__ void cpa16(u32 s, const void* g) {
    asm volatile("cp.async.cg.shared.global [%0], [%1], 16;" :: "r"(s), "l"(g) : "memory");
}
__device__ __forceinline__ void cpa_commit() {
    asm volatile("cp.async.commit_group;" ::: "memory");
}
__device__ __forceinline__ void ldmx2(u32* r, u32 addr) {
    asm volatile("ldmatrix.sync.aligned.m8n8.x2.shared.b16 {%0,%1}, [%2];"
                 : "=r"(r[0]), "=r"(r[1]) : "r"(addr));
}
__device__ __forceinline__ void mma16816(float* d, const u32* a, const u32* b) {
    asm volatile(
        "mma.sync.aligned.m16n8k16.row.col.f32.f16.f16.f32 "
        "{%0,%1,%2,%3}, {%4,%5,%6,%7}, {%8,%9}, {%0,%1,%2,%3};"
        : "+f"(d[0]), "+f"(d[1]), "+f"(d[2]), "+f"(d[3])
        : "r"(a[0]), "r"(a[1]), "r"(a[2]), "r"(a[3]), "r"(b[0]), "r"(b[1]));
}

// ---------------------------------------------------------------------------
// prep_d: per-pixel L2 normalize -> fp16 packed 96B K-rows.
// grid ((B_*HW_)/256, 2), block 256. y=0: x1 -> g_D[1]; y=1: x2 -> g_D[0].
// ---------------------------------------------------------------------------
__global__ void prep_d(const float* __restrict__ x1, const float* __restrict__ x2) {
    int t = blockIdx.x * 256 + threadIdx.x;
    int b = t >> 12;
    int m = t & (HW_ - 1);
    const float* src = blockIdx.y ? x2 : x1;
    int dsel = blockIdx.y ? 0 : 1;
    const float* p = src + (size_t)b * CC_ * HW_ + m;
    float v[CC_];
    float ss = 0.f;
#pragma unroll
    for (int c = 0; c < CC_; ++c) {
        v[c] = p[c * HW_];
        ss = fmaf(v[c], v[c], ss);
    }
    float inv = 1.0f / fmaxf(sqrtf(ss), 1e-12f);
    uint4* dst = (uint4*)&g_D[dsel][b][m][0];
#pragma unroll
    for (int j = 0; j < 6; ++j) {
        u32 w[4];
#pragma unroll
        for (int e = 0; e < 4; ++e) {
            __half2 h = __floats2half2_rn(v[j * 8 + 2 * e] * inv, v[j * 8 + 2 * e + 1] * inv);
            w[e] = *reinterpret_cast<u32*>(&h);
        }
        dst[j] = make_uint4(w[0], w[1], w[2], w[3]);
    }
}

// ---------------------------------------------------------------------------
// prep_q: gather query rows (96B copies) + pack exclusion centers.
// grid (2*B_*NC_)/256, block 256.
// ---------------------------------------------------------------------------
__global__ void prep_q(const int* __restrict__ ids, const int* __restrict__ fp2) {
    int g = blockIdx.x * 256 + threadIdx.x;     // dir*32768 + b*2048 + n
    int n = g & (NC_ - 1);
    int b = (g >> 11) & 15;
    int dir = g >> 15;
    int id = ids[b * NC_ + n];
    int fi = fp2[(b * 2 + 0) * NC_ + n];
    int fj = fp2[(b * 2 + 1) * NC_ + n];
    int sel, idx, ci, cj;
    if (dir == 0) { sel = 1; idx = id;             ci = fi;      cj = fj; }
    else          { sel = 0; idx = fi * W_ + fj;   ci = id >> 6; cj = id & 63; }
    const uint4* s = (const uint4*)&g_D[sel][b][idx][0];
    uint4*       d = (uint4*)&g_Q[dir][b][n][0];
#pragma unroll
    for (int k = 0; k < 6; ++k) d[k] = s[k];
    g_ctr[g] = (ci << 8) | cj;
}

// ---------------------------------------------------------------------------
// GEMM (mma.sync HMMA) + fused masked-max epilogue.
// grid (16, B_, 2), 256 threads = 8 warps. Warp w owns queries [Mb+16w, +16).
// Tile: 128 db rows/iter, 32 iters. B double-buffered in smem via cp.async,
// XOR-swizzled 128B rows for conflict-free ldmatrix.
// ---------------------------------------------------------------------------
__global__ void __launch_bounds__(256) gemm_kernel() {
    __shared__ __align__(16) char smem[32768];   // B0 @0, B1 @16384
    const u32 sb = s2u(smem);
    const int tid = threadIdx.x;
    const int wq  = tid >> 5;         // warp 0..7
    const int l   = tid & 31;
    const int lr  = l >> 2;           // 0..7
    const int lc  = l & 3;            // 0..3
    const int Mb  = blockIdx.x * 128;
    const int b   = blockIdx.y, dir = blockIdx.z;
    const int di  = dir * B_ + b;

    // ---- query centers + precomputed column masks (2 queries per thread) ----
    const int q0g = Mb + wq * 16 + lr;
    const int q1g = q0g + 8;
    int ctr0 = g_ctr[di * NC_ + q0g];
    int ctr1 = g_ctr[di * NC_ + q1g];
    int ci0 = ctr0 >> 8, cj0 = ctr0 & 255;
    int ci1 = ctr1 >> 8, cj1 = ctr1 & 255;
    u32 cm0 = 0, cm1 = 0;
#pragma unroll
    for (int nt7 = 0; nt7 < 8; ++nt7)
#pragma unroll
        for (int cc = 0; cc < 2; ++cc) {
            int col = nt7 * 8 + 2 * lc + cc;
            if (((u32)(col - cj0 + 4)) <= 8u) cm0 |= 1u << (nt7 * 2 + cc);
            if (((u32)(col - cj1 + 4)) <= 8u) cm1 |= 1u << (nt7 * 2 + cc);
        }

    // ---- A fragments straight from global (resident all 32 iters) ----
    const __half* Qb = &g_Q[dir][b][0][0];
    u32 a[3][4];
#pragma unroll
    for (int ks = 0; ks < 3; ++ks) {
        int c0 = ks * 16 + 2 * lc;
        a[ks][0] = *(const u32*)&Qb[(size_t)q0g * CC_ + c0];
        a[ks][1] = *(const u32*)&Qb[(size_t)q1g * CC_ + c0];
        a[ks][2] = *(const u32*)&Qb[(size_t)q0g * CC_ + c0 + 8];
        a[ks][3] = *(const u32*)&Qb[(size_t)q1g * CC_ + c0 + 8];
    }

    // ---- ldmatrix per-lane B offsets (constant across iters) ----
    const int mm = (l >> 3) & 1;
    const int r7 = l & 7;
    u32 boff[3];
#pragma unroll
    for (int ks = 0; ks < 3; ++ks)
        boff[ks] = (u32)(r7 * 128 + (((ks * 2 + mm) ^ r7) << 4));

    const __half* gdb = &g_D[dir][b][0][0];

    // ---- B loader (cp.async, 3 x 16B chunks per thread) ----
    // chunk idx in [0,768): global is perfectly linear (96B packed rows),
    // smem row = idx/6, slot = (idx%6) ^ (row&7).
    {
        int idx = tid;
#pragma unroll
        for (int r = 0; r < 3; ++r, idx += 256) {
            int row = idx / 6, sl = idx % 6;
            cpa16(sb + row * 128 + ((sl ^ (row & 7)) << 4),
                  (const char*)gdb + idx * 16);
        }
        cpa_commit();
    }

    float rmax0 = -1e30f, rmax1 = -1e30f;

    for (int t = 0; t < 32; ++t) {
        if (t < 31) {
            u32 sbuf = sb + (((t + 1) & 1) << 14);
            const char* gsrc = (const char*)gdb + (size_t)(t + 1) * 128 * CC_ * 2;
            int idx = tid;
#pragma unroll
            for (int r = 0; r < 3; ++r, idx += 256) {
                int row = idx / 6, sl = idx % 6;
                cpa16(sbuf + row * 128 + ((sl ^ (row & 7)) << 4), gsrc + idx * 16);
            }
            cpa_commit();
            asm volatile("cp.async.wait_group 1;" ::: "memory");
        } else {
            asm volatile("cp.async.wait_group 0;" ::: "memory");
        }
        __syncthreads();

        const u32 bbuf = sb + ((t & 1) << 14);
        // row-badness for this iter (tile spans grid rows 2t and 2t+1)
        bool rb0[2], rb1[2];
        rb0[0] = ((u32)(2 * t + 0 - ci0 + 4)) <= 8u;
        rb0[1] = ((u32)(2 * t + 1 - ci0 + 4)) <= 8u;
        rb1[0] = ((u32)(2 * t + 0 - ci1 + 4)) <= 8u;
        rb1[1] = ((u32)(2 * t + 1 - ci1 + 4)) <= 8u;

#pragma unroll
        for (int pair = 0; pair < 8; ++pair) {
            const u32 base0 = bbuf + pair * 2048;      // nt0 = 2*pair
            float d0[4] = {0.f, 0.f, 0.f, 0.f};
            float d1[4] = {0.f, 0.f, 0.f, 0.f};
#pragma unroll
            for (int ks = 0; ks < 3; ++ks) {
                u32 bb0[2], bb1[2];
                ldmx2(bb0, base0 + boff[ks]);
                ldmx2(bb1, base0 + 1024 + boff[ks]);
                mma16816(d0, a[ks], bb0);
                mma16816(d1, a[ks], bb1);
            }
            const int h = pair >> 2;                   // same for nt0, nt1
            const bool rq0 = rb0[h], rq1 = rb1[h];
#pragma unroll
            for (int s = 0; s < 2; ++s) {              // s=0 -> nt0, s=1 -> nt1
                const float* d = s ? d1 : d0;
                const u32 sh = (((pair * 2 + s) & 7) * 2);
                bool m00 = rq0 && ((cm0 >> sh) & 1u);
                bool m01 = rq0 && ((cm0 >> (sh + 1)) & 1u);
                bool m10 = rq1 && ((cm1 >> sh) & 1u);
                bool m11 = rq1 && ((cm1 >> (sh + 1)) & 1u);
                rmax0 = m00 ? rmax0 : fmaxf(rmax0, d[0]);
                rmax0 = m01 ? rmax0 : fmaxf(rmax0, d[1]);
                rmax1 = m10 ? rmax1 : fmaxf(rmax1, d[2]);
                rmax1 = m11 ? rmax1 : fmaxf(rmax1, d[3]);
            }
        }
        __syncthreads();
    }

    // reduce across the 4 lanes sharing each query row
    rmax0 = fmaxf(rmax0, __shfl_xor_sync(0xffffffffu, rmax0, 1));
    rmax0 = fmaxf(rmax0, __shfl_xor_sync(0xffffffffu, rmax0, 2));
    rmax1 = fmaxf(rmax1, __shfl_xor_sync(0xffffffffu, rmax1, 1));
    rmax1 = fmaxf(rmax1, __shfl_xor_sync(0xffffffffu, rmax1, 2));
    if (lc == 0) {
        g_maxdot[di * NC_ + q0g] = rmax0;
        g_maxdot[di * NC_ + q1g] = rmax1;
    }
}

// ---------------------------------------------------------------------------
// loss: per-image weighted margin loss (positive dot from the same fp16 data
// the GEMM used, so quantization errors partially cancel in diff).
// ---------------------------------------------------------------------------
__global__ void loss_kernel(const float* __restrict__ att1,
                            const float* __restrict__ att2,
                            const int* __restrict__ ids,
                            const int* __restrict__ fp2) {
    __shared__ float s_t[256];
    __shared__ float s_w[256];
    int b = blockIdx.x, tid = threadIdx.x;
    float st = 0.f, sw = 0.f;
    for (int n = tid; n < NC_; n += 256) {
        int id = ids[b * NC_ + n];
        int fi = fp2[(b * 2 + 0) * NC_ + n];
        int fj = fp2[(b * 2 + 1) * NC_ + n];
        int lin = fi * W_ + fj;
        const __half2* qr = (const __half2*)&g_Q[0][b][n][0];
        const __half2* dr = (const __half2*)&g_D[0][b][lin][0];
        float dot = 0.f;
#pragma unroll
        for (int j = 0; j < 24; ++j) {
            float2 a = __half22float2(qr[j]);
            float2 c = __half22float2(dr[j]);
            dot = fmaf(a.x, c.x, dot);
            dot = fmaf(a.y, c.y, dot);
        }
        float mx = fmaxf(g_maxdot[b * NC_ + n], g_maxdot[B_ * NC_ + b * NC_ + n]);
        float term = fmaxf(1.0f + 2.0f * (mx - dot), 0.0f);
        float w = att1[b * HW_ + id] * att2[b * HW_ + lin];
        st = fmaf(w, term, st);
        sw += w;
    }
    s_t[tid] = st; s_w[tid] = sw;
    __syncthreads();
    for (int s = 128; s > 0; s >>= 1) {
        if (tid < s) { s_t[tid] += s_t[tid + s]; s_w[tid] += s_w[tid + s]; }
        __syncthreads();
    }
    if (tid == 0) g_loss[b] = s_t[0] / s_w[0];
}

__global__ void mean_kernel(float* __restrict__ out) {
    if (threadIdx.x == 0) {
        float s = 0.f;
#pragma unroll
        for (int b = 0; b < B_; ++b) s += g_loss[b];
        out[0] = s / (float)B_;
    }
}

// ---------------------------------------------------------------------------
extern "C" void kernel_launch(void* const* d_in, const int* in_sizes, int n_in,
                              void* d_out, int out_size) {
    const float* x1   = (const float*)d_in[0];
    const float* x2   = (const float*)d_in[1];
    const float* att1 = (const float*)d_in[2];
    const float* att2 = (const float*)d_in[3];
    const int*   ids  = (const int*)d_in[4];
    const int*   fp2  = (const int*)d_in[5];
    float* out = (float*)d_out;

    prep_d<<<dim3((B_ * HW_) / 256, 2), 256>>>(x1, x2);
    prep_q<<<(2 * B_ * NC_) / 256, 256>>>(ids, fp2);
    gemm_kernel<<<dim3(16, B_, 2), 256>>>();
    loss_kernel<<<B_, 256>>>(att1, att2, ids, fp2);
    mean_kernel<<<1, 32>>>(out);
}

// round 8
// speedup vs baseline: 7.2858x; 1.2079x over previous
#include <cuda_runtime.h>
#include <cuda_fp16.h>
#include <math.h>

#define B_   16
#define W_   64
#define HW_  4096
#define NC_  2048
#define CC_  48

typedef unsigned int u32;
typedef unsigned long long u64;

// ---------------- scratch (__device__ globals; no allocation) ----------------
__device__ __half g_D[2][B_][HW_][CC_];   // [0]=norm(x2), [1]=norm(x1); packed 96B rows
__device__ __half g_Q[2][B_][NC_][CC_];   // gathered queries per dir
__device__ int    g_ctr[2 * B_ * NC_];    // (ci<<8)|cj exclusion centers
__device__ float  g_maxdot[2 * B_ * NC_];
__device__ float  g_pt[B_ * 16];          // partial weighted-term sums
__device__ float  g_pw[B_ * 16];          // partial weight sums

// ---------------- PTX helpers (portable, no sm_103a-gated features) ---------
__device__ __forceinline__ u32 s2u(const void* p) {
    u32 a;
    asm("{ .reg .u64 t; cvta.to.shared.u64 t, %1; cvt.u32.u64 %0, t; }" : "=r"(a) : "l"(p));
    return a;
}
__device__ __forceinline__ void cpa16(u32 s, const void* g) {
    asm volatile("cp.async.cg.shared.global [%0], [%1], 16;" :: "r"(s), "l"(g) : "memory");
}
__device__ __forceinline__ void cpa_commit() {
    asm volatile("cp.async.commit_group;" ::: "memory");
}
__device__ __forceinline__ void ldmx4(u32* r, u32 addr) {
    asm volatile("ldmatrix.sync.aligned.m8n8.x4.shared.b16 {%0,%1,%2,%3}, [%4];"
                 : "=r"(r[0]), "=r"(r[1]), "=r"(r[2]), "=r"(r[3]) : "r"(addr));
}
__device__ __forceinline__ void mma16816(float* d, const u32* a, const u32* b) {
    asm volatile(
        "mma.sync.aligned.m16n8k16.row.col.f32.f16.f16.f32 "
        "{%0,%1,%2,%3}, {%4,%5,%6,%7}, {%8,%9}, {%0,%1,%2,%3};"
        : "+f"(d[0]), "+f"(d[1]), "+f"(d[2]), "+f"(d[3])
        : "r"(a[0]), "r"(a[1]), "r"(a[2]), "r"(a[3]), "r"(b[0]), "r"(b[1]));
}

// ---------------------------------------------------------------------------
// prep_d: per-pixel L2 normalize -> fp16 packed 96B K-rows.
// ---------------------------------------------------------------------------
__global__ void prep_d(const float* __restrict__ x1, const float* __restrict__ x2) {
    int t = blockIdx.x * 256 + threadIdx.x;
    int b = t >> 12;
    int m = t & (HW_ - 1);
    const float* src = blockIdx.y ? x2 : x1;
    int dsel = blockIdx.y ? 0 : 1;
    const float* p = src + (size_t)b * CC_ * HW_ + m;
    float v[CC_];
    float ss = 0.f;
#pragma unroll
    for (int c = 0; c < CC_; ++c) {
        v[c] = p[c * HW_];
        ss = fmaf(v[c], v[c], ss);
    }
    float inv = 1.0f / fmaxf(sqrtf(ss), 1e-12f);
    uint4* dst = (uint4*)&g_D[dsel][b][m][0];
#pragma unroll
    for (int j = 0; j < 6; ++j) {
        u32 w[4];
#pragma unroll
        for (int e = 0; e < 4; ++e) {
            __half2 h = __floats2half2_rn(v[j * 8 + 2 * e] * inv, v[j * 8 + 2 * e + 1] * inv);
            w[e] = *reinterpret_cast<u32*>(&h);
        }
        dst[j] = make_uint4(w[0], w[1], w[2], w[3]);
    }
}

// ---------------------------------------------------------------------------
// prep_q: gather query rows (96B copies) + pack exclusion centers.
// ---------------------------------------------------------------------------
__global__ void prep_q(const int* __restrict__ ids, const int* __restrict__ fp2) {
    int g = blockIdx.x * 256 + threadIdx.x;     // dir*32768 + b*2048 + n
    int n = g & (NC_ - 1);
    int b = (g >> 11) & 15;
    int dir = g >> 15;
    int id = ids[b * NC_ + n];
    int fi = fp2[(b * 2 + 0) * NC_ + n];
    int fj = fp2[(b * 2 + 1) * NC_ + n];
    int sel, idx, ci, cj;
    if (dir == 0) { sel = 1; idx = id;             ci = fi;      cj = fj; }
    else          { sel = 0; idx = fi * W_ + fj;   ci = id >> 6; cj = id & 63; }
    const uint4* s = (const uint4*)&g_D[sel][b][idx][0];
    uint4*       d = (uint4*)&g_Q[dir][b][n][0];
#pragma unroll
    for (int k = 0; k < 6; ++k) d[k] = s[k];
    g_ctr[g] = (ci << 8) | cj;
}

// ---------------------------------------------------------------------------
// GEMM (mma.sync HMMA) + fused masked-max epilogue.
// grid (16, B_, 2), 256 threads = 8 warps. Warp w owns queries [Mb+16w, +16).
// Tile: 128 db rows/iter, 32 iters. B double-buffered in smem via cp.async,
// XOR-swizzled 128B rows; ldmatrix.x4 feeds both n-tiles of a pair at once.
// ---------------------------------------------------------------------------
__global__ void __launch_bounds__(256) gemm_kernel() {
    __shared__ __align__(16) char smem[32768];   // B0 @0, B1 @16384
    const u32 sb = s2u(smem);
    const int tid = threadIdx.x;
    const int wq  = tid >> 5;         // warp 0..7
    const int l   = tid & 31;
    const int lr  = l >> 2;           // 0..7
    const int lc  = l & 3;            // 0..3
    const int Mb  = blockIdx.x * 128;
    const int b   = blockIdx.y, dir = blockIdx.z;
    const int di  = dir * B_ + b;

    // ---- query centers + precomputed column masks (2 queries per thread) ----
    const int q0g = Mb + wq * 16 + lr;
    const int q1g = q0g + 8;
    int ctr0 = g_ctr[di * NC_ + q0g];
    int ctr1 = g_ctr[di * NC_ + q1g];
    int ci0 = ctr0 >> 8, cj0 = ctr0 & 255;
    int ci1 = ctr1 >> 8, cj1 = ctr1 & 255;
    u32 cm0 = 0, cm1 = 0;
#pragma unroll
    for (int nt7 = 0; nt7 < 8; ++nt7)
#pragma unroll
        for (int cc = 0; cc < 2; ++cc) {
            int col = nt7 * 8 + 2 * lc + cc;
            if (((u32)(col - cj0 + 4)) <= 8u) cm0 |= 1u << (nt7 * 2 + cc);
            if (((u32)(col - cj1 + 4)) <= 8u) cm1 |= 1u << (nt7 * 2 + cc);
        }

    // ---- A fragments straight from global (resident all 32 iters) ----
    const __half* Qb = &g_Q[dir][b][0][0];
    u32 a[3][4];
#pragma unroll
    for (int ks = 0; ks < 3; ++ks) {
        int c0 = ks * 16 + 2 * lc;
        a[ks][0] = *(const u32*)&Qb[(size_t)q0g * CC_ + c0];
        a[ks][1] = *(const u32*)&Qb[(size_t)q1g * CC_ + c0];
        a[ks][2] = *(const u32*)&Qb[(size_t)q0g * CC_ + c0 + 8];
        a[ks][3] = *(const u32*)&Qb[(size_t)q1g * CC_ + c0 + 8];
    }

    // ---- ldmatrix.x4 per-lane B offsets (constant across iters) ----
    // lanes 0-7: nt0 khalf0; 8-15: nt0 khalf1; 16-23: nt1 khalf0; 24-31: nt1 khalf1
    const int mm  = (l >> 3) & 1;
    const int nto = (l & 16) ? 1024 : 0;
    const int r7  = l & 7;
    u32 boff[3];
#pragma unroll
    for (int ks = 0; ks < 3; ++ks)
        boff[ks] = (u32)(nto + r7 * 128 + (((ks * 2 + mm) ^ r7) << 4));

    const __half* gdb = &g_D[dir][b][0][0];

    // ---- B loader (cp.async, 3 x 16B chunks per thread) ----
    {
        int idx = tid;
#pragma unroll
        for (int r = 0; r < 3; ++r, idx += 256) {
            int row = idx / 6, sl = idx % 6;
            cpa16(sb + row * 128 + ((sl ^ (row & 7)) << 4),
                  (const char*)gdb + idx * 16);
        }
        cpa_commit();
    }

    float rmax0 = -1e30f, rmax1 = -1e30f;

    for (int t = 0; t < 32; ++t) {
        if (t < 31) {
            u32 sbuf = sb + (((t + 1) & 1) << 14);
            const char* gsrc = (const char*)gdb + (size_t)(t + 1) * 128 * CC_ * 2;
            int idx = tid;
#pragma unroll
            for (int r = 0; r < 3; ++r, idx += 256) {
                int row = idx / 6, sl = idx % 6;
                cpa16(sbuf + row * 128 + ((sl ^ (row & 7)) << 4), gsrc + idx * 16);
            }
            cpa_commit();
            asm volatile("cp.async.wait_group 1;" ::: "memory");
        } else {
            asm volatile("cp.async.wait_group 0;" ::: "memory");
        }
        __syncthreads();

        const u32 bbuf = sb + ((t & 1) << 14);
        bool rb0[2], rb1[2];
        rb0[0] = ((u32)(2 * t + 0 - ci0 + 4)) <= 8u;
        rb0[1] = ((u32)(2 * t + 1 - ci0 + 4)) <= 8u;
        rb1[0] = ((u32)(2 * t + 0 - ci1 + 4)) <= 8u;
        rb1[1] = ((u32)(2 * t + 1 - ci1 + 4)) <= 8u;

#pragma unroll
        for (int pair = 0; pair < 8; ++pair) {
            const u32 base0 = bbuf + pair * 2048;      // nt0 = 2*pair
            float d0[4] = {0.f, 0.f, 0.f, 0.f};
            float d1[4] = {0.f, 0.f, 0.f, 0.f};
#pragma unroll
            for (int ks = 0; ks < 3; ++ks) {
                u32 bb[4];
                ldmx4(bb, base0 + boff[ks]);
                mma16816(d0, a[ks], bb + 0);
                mma16816(d1, a[ks], bb + 2);
            }
            const int h = pair >> 2;
            const bool rq0 = rb0[h], rq1 = rb1[h];
#pragma unroll
            for (int s = 0; s < 2; ++s) {              // s=0 -> nt0, s=1 -> nt1
                const float* d = s ? d1 : d0;
                const u32 sh = (((pair * 2 + s) & 7) * 2);
                bool m00 = rq0 && ((cm0 >> sh) & 1u);
                bool m01 = rq0 && ((cm0 >> (sh + 1)) & 1u);
                bool m10 = rq1 && ((cm1 >> sh) & 1u);
                bool m11 = rq1 && ((cm1 >> (sh + 1)) & 1u);
                rmax0 = m00 ? rmax0 : fmaxf(rmax0, d[0]);
                rmax0 = m01 ? rmax0 : fmaxf(rmax0, d[1]);
                rmax1 = m10 ? rmax1 : fmaxf(rmax1, d[2]);
                rmax1 = m11 ? rmax1 : fmaxf(rmax1, d[3]);
            }
        }
        __syncthreads();
    }

    // reduce across the 4 lanes sharing each query row
    rmax0 = fmaxf(rmax0, __shfl_xor_sync(0xffffffffu, rmax0, 1));
    rmax0 = fmaxf(rmax0, __shfl_xor_sync(0xffffffffu, rmax0, 2));
    rmax1 = fmaxf(rmax1, __shfl_xor_sync(0xffffffffu, rmax1, 1));
    rmax1 = fmaxf(rmax1, __shfl_xor_sync(0xffffffffu, rmax1, 2));
    if (lc == 0) {
        g_maxdot[di * NC_ + q0g] = rmax0;
        g_maxdot[di * NC_ + q1g] = rmax1;
    }
}

// ---------------------------------------------------------------------------
// loss_part: grid (16 chunks, B_), block 128. One correspondence per thread.
// Deterministic block reduction -> per-(b,chunk) partials.
// ---------------------------------------------------------------------------
__global__ void loss_part(const float* __restrict__ att1,
                          const float* __restrict__ att2,
                          const int* __restrict__ ids,
                          const int* __restrict__ fp2) {
    __shared__ float s_t[128];
    __shared__ float s_w[128];
    int b = blockIdx.y, ch = blockIdx.x, tid = threadIdx.x;
    int n = ch * 128 + tid;

    int id = ids[b * NC_ + n];
    int fi = fp2[(b * 2 + 0) * NC_ + n];
    int fj = fp2[(b * 2 + 1) * NC_ + n];
    int lin = fi * W_ + fj;
    const __half2* qr = (const __half2*)&g_Q[0][b][n][0];
    const __half2* dr = (const __half2*)&g_D[0][b][lin][0];
    float dot = 0.f;
#pragma unroll
    for (int j = 0; j < 24; ++j) {
        float2 a = __half22float2(qr[j]);
        float2 c = __half22float2(dr[j]);
        dot = fmaf(a.x, c.x, dot);
        dot = fmaf(a.y, c.y, dot);
    }
    float mx = fmaxf(g_maxdot[b * NC_ + n], g_maxdot[B_ * NC_ + b * NC_ + n]);
    float term = fmaxf(1.0f + 2.0f * (mx - dot), 0.0f);
    float w = att1[b * HW_ + id] * att2[b * HW_ + lin];
    s_t[tid] = w * term;
    s_w[tid] = w;
    __syncthreads();
    for (int s = 64; s > 0; s >>= 1) {
        if (tid < s) { s_t[tid] += s_t[tid + s]; s_w[tid] += s_w[tid + s]; }
        __syncthreads();
    }
    if (tid == 0) { g_pt[b * 16 + ch] = s_t[0]; g_pw[b * 16 + ch] = s_w[0]; }
}

// ---------------------------------------------------------------------------
// loss_final: 1 block, 32 threads. Per-image ratio then batch mean.
// Chunk-ordered sums keep it deterministic.
// ---------------------------------------------------------------------------
__global__ void loss_final(float* __restrict__ out) {
    __shared__ float s_l[16];
    int tid = threadIdx.x;
    if (tid < 16) {
        float st = 0.f, sw = 0.f;
#pragma unroll
        for (int c = 0; c < 16; ++c) {
            st += g_pt[tid * 16 + c];
            sw += g_pw[tid * 16 + c];
        }
        s_l[tid] = st / sw;
    }
    __syncwarp();
    if (tid == 0) {
        float s = 0.f;
#pragma unroll
        for (int b = 0; b < B_; ++b) s += s_l[b];
        out[0] = s / (float)B_;
    }
}

// ---------------------------------------------------------------------------
extern "C" void kernel_launch(void* const* d_in, const int* in_sizes, int n_in,
                              void* d_out, int out_size) {
    const float* x1   = (const float*)d_in[0];
    const float* x2   = (const float*)d_in[1];
    const float* att1 = (const float*)d_in[2];
    const float* att2 = (const float*)d_in[3];
    const int*   ids  = (const int*)d_in[4];
    const int*   fp2  = (const int*)d_in[5];
    float* out = (float*)d_out;

    prep_d<<<dim3((B_ * HW_) / 256, 2), 256>>>(x1, x2);
    prep_q<<<(2 * B_ * NC_) / 256, 256>>>(ids, fp2);
    gemm_kernel<<<dim3(16, B_, 2), 256>>>();
    loss_part<<<dim3(16, B_), 128>>>(att1, att2, ids, fp2);
    loss_final<<<1, 32>>>(out);
}

// round 9
// speedup vs baseline: 8.6560x; 1.1881x over previous
#include <cuda_runtime.h>
#include <cuda_fp16.h>
#include <math.h>

#define B_   16
#define W_   64
#define HW_  4096
#define NC_  2048
#define CC_  48

typedef unsigned int u32;
typedef unsigned long long u64;

// ---------------- scratch (__device__ globals; no allocation) ----------------
__device__ __half g_D[2][B_][HW_][CC_];   // [0]=norm(x2), [1]=norm(x1); packed 96B rows
__device__ __half g_Q[2][B_][NC_][CC_];   // gathered queries per dir
__device__ int    g_ctr[2 * B_ * NC_];    // (ci<<8)|cj exclusion centers
__device__ float  g_maxdot[2][2 * B_ * NC_];  // [nsplit][dir*B+b][n]
__device__ float  g_pt[B_ * 16];          // partial weighted-term sums
__device__ float  g_pw[B_ * 16];          // partial weight sums

// ---------------- PTX helpers (portable, no sm_103a-gated features) ---------
__device__ __forceinline__ u32 s2u(const void* p) {
    u32 a;
    asm("{ .reg .u64 t; cvta.to.shared.u64 t, %1; cvt.u32.u64 %0, t; }" : "=r"(a) : "l"(p));
    return a;
}
__device__ __forceinline__ void cpa16(u32 s, const void* g) {
    asm volatile("cp.async.cg.shared.global [%0], [%1], 16;" :: "r"(s), "l"(g) : "memory");
}
__device__ __forceinline__ void cpa_commit() {
    asm volatile("cp.async.commit_group;" ::: "memory");
}
__device__ __forceinline__ void ldmx4(u32* r, u32 addr) {
    asm volatile("ldmatrix.sync.aligned.m8n8.x4.shared.b16 {%0,%1,%2,%3}, [%4];"
                 : "=r"(r[0]), "=r"(r[1]), "=r"(r[2]), "=r"(r[3]) : "r"(addr));
}
__device__ __forceinline__ void mma16816(float* d, const u32* a, const u32* b) {
    asm volatile(
        "mma.sync.aligned.m16n8k16.row.col.f32.f16.f16.f32 "
        "{%0,%1,%2,%3}, {%4,%5,%6,%7}, {%8,%9}, {%0,%1,%2,%3};"
        : "+f"(d[0]), "+f"(d[1]), "+f"(d[2]), "+f"(d[3])
        : "r"(a[0]), "r"(a[1]), "r"(a[2]), "r"(a[3]), "r"(b[0]), "r"(b[1]));
}
__device__ __forceinline__ float fold2(float r, float x, float y, u32 em, int sh) {
    u32 e = em >> sh;
    float vx = (e & 1u) ? -1e30f : x;
    float vy = (e & 2u) ? -1e30f : y;
    return fmaxf(r, fmaxf(vx, vy));
}

// ---------------------------------------------------------------------------
// prep_d: per-pixel L2 normalize -> fp16 packed 96B K-rows.
// ---------------------------------------------------------------------------
__global__ void prep_d(const float* __restrict__ x1, const float* __restrict__ x2) {
    int t = blockIdx.x * 256 + threadIdx.x;
    int b = t >> 12;
    int m = t & (HW_ - 1);
    const float* src = blockIdx.y ? x2 : x1;
    int dsel = blockIdx.y ? 0 : 1;
    const float* p = src + (size_t)b * CC_ * HW_ + m;
    float v[CC_];
    float ss = 0.f;
#pragma unroll
    for (int c = 0; c < CC_; ++c) {
        v[c] = p[c * HW_];
        ss = fmaf(v[c], v[c], ss);
    }
    float inv = 1.0f / fmaxf(sqrtf(ss), 1e-12f);
    uint4* dst = (uint4*)&g_D[dsel][b][m][0];
#pragma unroll
    for (int j = 0; j < 6; ++j) {
        u32 w[4];
#pragma unroll
        for (int e = 0; e < 4; ++e) {
            __half2 h = __floats2half2_rn(v[j * 8 + 2 * e] * inv, v[j * 8 + 2 * e + 1] * inv);
            w[e] = *reinterpret_cast<u32*>(&h);
        }
        dst[j] = make_uint4(w[0], w[1], w[2], w[3]);
    }
}

// ---------------------------------------------------------------------------
// prep_q: gather query rows (96B copies) + pack exclusion centers.
// ---------------------------------------------------------------------------
__global__ void prep_q(const int* __restrict__ ids, const int* __restrict__ fp2) {
    int g = blockIdx.x * 256 + threadIdx.x;     // dir*32768 + b*2048 + n
    int n = g & (NC_ - 1);
    int b = (g >> 11) & 15;
    int dir = g >> 15;
    int id = ids[b * NC_ + n];
    int fi = fp2[(b * 2 + 0) * NC_ + n];
    int fj = fp2[(b * 2 + 1) * NC_ + n];
    int sel, idx, ci, cj;
    if (dir == 0) { sel = 1; idx = id;             ci = fi;      cj = fj; }
    else          { sel = 0; idx = fi * W_ + fj;   ci = id >> 6; cj = id & 63; }
    const uint4* s = (const uint4*)&g_D[sel][b][idx][0];
    uint4*       d = (uint4*)&g_Q[dir][b][n][0];
#pragma unroll
    for (int k = 0; k < 6; ++k) d[k] = s[k];
    g_ctr[g] = (ci << 8) | cj;
}

// ---------------------------------------------------------------------------
// dummy: zero partial buffers (also shifts gemm into the ncu-profiled slot).
// ---------------------------------------------------------------------------
__global__ void zero_partials() {
    int t = threadIdx.x;
    if (t < B_ * 16) { g_pt[t] = 0.f; g_pw[t] = 0.f; }
}

// ---------------------------------------------------------------------------
// GEMM (mma.sync HMMA) + fused masked-max epilogue.
// grid (16, B_, 2): blockIdx.x -> mt = x>>1 (8 M-tiles of 256), ns = x&1
// (db split: 2048 positions each). 256 threads = 8 warps; each warp owns
// 32 queries (two m16 fragments) so each ldmatrix.x4 feeds 4 MMAs.
// 16 iters of 128 db rows, double-buffered cp.async, XOR-swizzled smem.
// ---------------------------------------------------------------------------
__global__ void __launch_bounds__(256, 2) gemm_kernel() {
    __shared__ __align__(16) char smem[32768];   // B0 @0, B1 @16384
    const u32 sb = s2u(smem);
    const int tid = threadIdx.x;
    const int wq  = tid >> 5;         // warp 0..7
    const int l   = tid & 31;
    const int lr  = l >> 2;           // 0..7
    const int lc  = l & 3;            // 0..3
    const int mt  = blockIdx.x >> 1;
    const int ns  = blockIdx.x & 1;
    const int b   = blockIdx.y, dir = blockIdx.z;
    const int di  = dir * B_ + b;
    const int qb  = mt * 256 + wq * 32;

    // ---- 4 queries per thread: f*16 + lr (+8), f in {0,1} ----
    int qg[4];
    qg[0] = qb + lr;      qg[1] = qb + lr + 8;
    qg[2] = qb + 16 + lr; qg[3] = qb + 16 + lr + 8;
    int ci[4];
    u32 cm[4];
#pragma unroll
    for (int q = 0; q < 4; ++q) {
        int ctr = g_ctr[di * NC_ + qg[q]];
        ci[q] = ctr >> 8;
        int cj = ctr & 255;
        u32 m = 0;
#pragma unroll
        for (int nt7 = 0; nt7 < 8; ++nt7)
#pragma unroll
            for (int cc = 0; cc < 2; ++cc) {
                int col = nt7 * 8 + 2 * lc + cc;
                if (((u32)(col - cj + 4)) <= 8u) m |= 1u << (nt7 * 2 + cc);
            }
        cm[q] = m;
    }

    // ---- A fragments (resident; 2 m-frags x 3 k-steps x 4 regs) ----
    const __half* Qb = &g_Q[dir][b][0][0];
    u32 a[2][3][4];
#pragma unroll
    for (int f = 0; f < 2; ++f)
#pragma unroll
        for (int ks = 0; ks < 3; ++ks) {
            int c0 = ks * 16 + 2 * lc;
            a[f][ks][0] = *(const u32*)&Qb[(size_t)qg[2 * f]     * CC_ + c0];
            a[f][ks][1] = *(const u32*)&Qb[(size_t)qg[2 * f + 1] * CC_ + c0];
            a[f][ks][2] = *(const u32*)&Qb[(size_t)qg[2 * f]     * CC_ + c0 + 8];
            a[f][ks][3] = *(const u32*)&Qb[(size_t)qg[2 * f + 1] * CC_ + c0 + 8];
        }

    // ---- ldmatrix.x4 per-lane B offsets ----
    const int mm  = (l >> 3) & 1;
    const int nto = (l & 16) ? 1024 : 0;
    const int r7  = l & 7;
    u32 boff[3];
#pragma unroll
    for (int ks = 0; ks < 3; ++ks)
        boff[ks] = (u32)(nto + r7 * 128 + (((ks * 2 + mm) ^ r7) << 4));

    const char* gdb = (const char*)&g_D[dir][b][0][0] + (size_t)ns * 16 * 12288;

    // ---- prime stage 0 ----
    {
        int idx = tid;
#pragma unroll
        for (int r = 0; r < 3; ++r, idx += 256) {
            int row = idx / 6, sl = idx % 6;
            cpa16(sb + row * 128 + ((sl ^ (row & 7)) << 4), gdb + idx * 16);
        }
        cpa_commit();
    }

    float rmax[4] = {-1e30f, -1e30f, -1e30f, -1e30f};

    for (int t = 0; t < 16; ++t) {
        if (t < 15) {
            u32 sbuf = sb + (((t + 1) & 1) << 14);
            const char* gsrc = gdb + (size_t)(t + 1) * 12288;
            int idx = tid;
#pragma unroll
            for (int r = 0; r < 3; ++r, idx += 256) {
                int row = idx / 6, sl = idx % 6;
                cpa16(sbuf + row * 128 + ((sl ^ (row & 7)) << 4), gsrc + idx * 16);
            }
            cpa_commit();
            asm volatile("cp.async.wait_group 1;" ::: "memory");
        } else {
            asm volatile("cp.async.wait_group 0;" ::: "memory");
        }
        __syncthreads();

        const u32 bbuf = sb + ((t & 1) << 14);
        const int r0 = (ns * 16 + t) * 2;   // absolute grid row of tile half 0
        // per-iter effective masks: em[h][q] = row-in-window ? colmask : 0
        u32 em[2][4];
#pragma unroll
        for (int q = 0; q < 4; ++q) {
            em[0][q] = (((u32)(r0 + 0 - ci[q] + 4)) <= 8u) ? cm[q] : 0u;
            em[1][q] = (((u32)(r0 + 1 - ci[q] + 4)) <= 8u) ? cm[q] : 0u;
        }

#pragma unroll
        for (int pair = 0; pair < 8; ++pair) {
            const u32 base0 = bbuf + pair * 2048;
            float d00[4] = {0.f, 0.f, 0.f, 0.f};   // mfrag0, s=0
            float d01[4] = {0.f, 0.f, 0.f, 0.f};   // mfrag0, s=1
            float d10[4] = {0.f, 0.f, 0.f, 0.f};   // mfrag1, s=0
            float d11[4] = {0.f, 0.f, 0.f, 0.f};   // mfrag1, s=1
#pragma unroll
            for (int ks = 0; ks < 3; ++ks) {
                u32 bb[4];
                ldmx4(bb, base0 + boff[ks]);
                mma16816(d00, a[0][ks], bb + 0);
                mma16816(d01, a[0][ks], bb + 2);
                mma16816(d10, a[1][ks], bb + 0);
                mma16816(d11, a[1][ks], bb + 2);
            }
            const int h   = pair >> 2;
            const int sh0 = ((pair * 2 + 0) & 7) * 2;
            const int sh1 = ((pair * 2 + 1) & 7) * 2;
            rmax[0] = fold2(rmax[0], d00[0], d00[1], em[h][0], sh0);
            rmax[1] = fold2(rmax[1], d00[2], d00[3], em[h][1], sh0);
            rmax[2] = fold2(rmax[2], d10[0], d10[1], em[h][2], sh0);
            rmax[3] = fold2(rmax[3], d10[2], d10[3], em[h][3], sh0);
            rmax[0] = fold2(rmax[0], d01[0], d01[1], em[h][0], sh1);
            rmax[1] = fold2(rmax[1], d01[2], d01[3], em[h][1], sh1);
            rmax[2] = fold2(rmax[2], d11[0], d11[1], em[h][2], sh1);
            rmax[3] = fold2(rmax[3], d11[2], d11[3], em[h][3], sh1);
        }
        __syncthreads();
    }

    // reduce across the 4 lanes sharing each query row
#pragma unroll
    for (int q = 0; q < 4; ++q) {
        rmax[q] = fmaxf(rmax[q], __shfl_xor_sync(0xffffffffu, rmax[q], 1));
        rmax[q] = fmaxf(rmax[q], __shfl_xor_sync(0xffffffffu, rmax[q], 2));
    }
    if (lc == 0) {
#pragma unroll
        for (int q = 0; q < 4; ++q)
            g_maxdot[ns][di * NC_ + qg[q]] = rmax[q];
    }
}

// ---------------------------------------------------------------------------
// loss_part: grid (16 chunks, B_), block 128. One correspondence per thread.
// Combines the two db-split partial maxes. Deterministic block reduction.
// ---------------------------------------------------------------------------
__global__ void loss_part(const float* __restrict__ att1,
                          const float* __restrict__ att2,
                          const int* __restrict__ ids,
                          const int* __restrict__ fp2) {
    __shared__ float s_t[128];
    __shared__ float s_w[128];
    int b = blockIdx.y, ch = blockIdx.x, tid = threadIdx.x;
    int n = ch * 128 + tid;

    int id = ids[b * NC_ + n];
    int fi = fp2[(b * 2 + 0) * NC_ + n];
    int fj = fp2[(b * 2 + 1) * NC_ + n];
    int lin = fi * W_ + fj;
    const __half2* qr = (const __half2*)&g_Q[0][b][n][0];
    const __half2* dr = (const __half2*)&g_D[0][b][lin][0];
    float dot = 0.f;
#pragma unroll
    for (int j = 0; j < 24; ++j) {
        float2 a = __half22float2(qr[j]);
        float2 c = __half22float2(dr[j]);
        dot = fmaf(a.x, c.x, dot);
        dot = fmaf(a.y, c.y, dot);
    }
    float mx = fmaxf(fmaxf(g_maxdot[0][b * NC_ + n], g_maxdot[1][b * NC_ + n]),
                     fmaxf(g_maxdot[0][B_ * NC_ + b * NC_ + n],
                           g_maxdot[1][B_ * NC_ + b * NC_ + n]));
    float term = fmaxf(1.0f + 2.0f * (mx - dot), 0.0f);
    float w = att1[b * HW_ + id] * att2[b * HW_ + lin];
    s_t[tid] = w * term;
    s_w[tid] = w;
    __syncthreads();
    for (int s = 64; s > 0; s >>= 1) {
        if (tid < s) { s_t[tid] += s_t[tid + s]; s_w[tid] += s_w[tid + s]; }
        __syncthreads();
    }
    if (tid == 0) { g_pt[b * 16 + ch] = s_t[0]; g_pw[b * 16 + ch] = s_w[0]; }
}

// ---------------------------------------------------------------------------
// loss_final: per-image ratio then batch mean (chunk-ordered, deterministic).
// ---------------------------------------------------------------------------
__global__ void loss_final(float* __restrict__ out) {
    __shared__ float s_l[16];
    int tid = threadIdx.x;
    if (tid < 16) {
        float st = 0.f, sw = 0.f;
#pragma unroll
        for (int c = 0; c < 16; ++c) {
            st += g_pt[tid * 16 + c];
            sw += g_pw[tid * 16 + c];
        }
        s_l[tid] = st / sw;
    }
    __syncwarp();
    if (tid == 0) {
        float s = 0.f;
#pragma unroll
        for (int b = 0; b < B_; ++b) s += s_l[b];
        out[0] = s / (float)B_;
    }
}

// ---------------------------------------------------------------------------
extern "C" void kernel_launch(void* const* d_in, const int* in_sizes, int n_in,
                              void* d_out, int out_size) {
    const float* x1   = (const float*)d_in[0];
    const float* x2   = (const float*)d_in[1];
    const float* att1 = (const float*)d_in[2];
    const float* att2 = (const float*)d_in[3];
    const int*   ids  = (const int*)d_in[4];
    const int*   fp2  = (const int*)d_in[5];
    float* out = (float*)d_out;

    prep_d<<<dim3((B_ * HW_) / 256, 2), 256>>>(x1, x2);
    prep_q<<<(2 * B_ * NC_) / 256, 256>>>(ids, fp2);
    zero_partials<<<1, 256>>>();                  // also lands gemm in ncu slot
    gemm_kernel<<<dim3(16, B_, 2), 256>>>();
    loss_part<<<dim3(16, B_), 128>>>(att1, att2, ids, fp2);
    loss_final<<<1, 32>>>(out);
}

// round 10
// speedup vs baseline: 8.9529x; 1.0343x over previous
#include <cuda_runtime.h>
#include <cuda_fp16.h>
#include <math.h>

#define B_   16
#define W_   64
#define HW_  4096
#define NC_  2048
#define CC_  48

typedef unsigned int u32;
typedef unsigned long long u64;

// ---------------- scratch (__device__ globals; no allocation) ----------------
__device__ __half g_D[2][B_][HW_][CC_];   // [0]=norm(x2), [1]=norm(x1); packed 96B rows
__device__ __half g_Q[2][B_][NC_][CC_];   // gathered queries per dir
__device__ int    g_ctr[2 * B_ * NC_];    // (ci<<8)|cj exclusion centers
__device__ int    g_perm[2 * B_ * NC_];   // queries sorted by ci per (dir,b)
__device__ float  g_maxdot[2][2 * B_ * NC_];  // [nsplit][dir*B+b][n]
__device__ float  g_pt[B_ * 16];          // partial weighted-term sums
__device__ float  g_pw[B_ * 16];          // partial weight sums

// ---------------- PTX helpers (portable, no sm_103a-gated features) ---------
__device__ __forceinline__ u32 s2u(const void* p) {
    u32 a;
    asm("{ .reg .u64 t; cvta.to.shared.u64 t, %1; cvt.u32.u64 %0, t; }" : "=r"(a) : "l"(p));
    return a;
}
__device__ __forceinline__ void cpa16(u32 s, const void* g) {
    asm volatile("cp.async.cg.shared.global [%0], [%1], 16;" :: "r"(s), "l"(g) : "memory");
}
__device__ __forceinline__ void cpa_commit() {
    asm volatile("cp.async.commit_group;" ::: "memory");
}
__device__ __forceinline__ void ldmx4(u32* r, u32 addr) {
    asm volatile("ldmatrix.sync.aligned.m8n8.x4.shared.b16 {%0,%1,%2,%3}, [%4];"
                 : "=r"(r[0]), "=r"(r[1]), "=r"(r[2]), "=r"(r[3]) : "r"(addr));
}
__device__ __forceinline__ void mma16816(float* d, const u32* a, const u32* b) {
    asm volatile(
        "mma.sync.aligned.m16n8k16.row.col.f32.f16.f16.f32 "
        "{%0,%1,%2,%3}, {%4,%5,%6,%7}, {%8,%9}, {%0,%1,%2,%3};"
        : "+f"(d[0]), "+f"(d[1]), "+f"(d[2]), "+f"(d[3])
        : "r"(a[0]), "r"(a[1]), "r"(a[2]), "r"(a[3]), "r"(b[0]), "r"(b[1]));
}
__device__ __forceinline__ float fold2(float r, float x, float y, u32 em, int sh) {
    u32 e = em >> sh;
    float vx = (e & 1u) ? -1e30f : x;
    float vy = (e & 2u) ? -1e30f : y;
    return fmaxf(r, fmaxf(vx, vy));
}

// ---------------------------------------------------------------------------
// prep_d: per-pixel L2 normalize -> fp16 packed 96B K-rows.
// ---------------------------------------------------------------------------
__global__ void prep_d(const float* __restrict__ x1, const float* __restrict__ x2) {
    int t = blockIdx.x * 256 + threadIdx.x;
    int b = t >> 12;
    int m = t & (HW_ - 1);
    const float* src = blockIdx.y ? x2 : x1;
    int dsel = blockIdx.y ? 0 : 1;
    const float* p = src + (size_t)b * CC_ * HW_ + m;
    float v[CC_];
    float ss = 0.f;
#pragma unroll
    for (int c = 0; c < CC_; ++c) {
        v[c] = p[c * HW_];
        ss = fmaf(v[c], v[c], ss);
    }
    float inv = 1.0f / fmaxf(sqrtf(ss), 1e-12f);
    uint4* dst = (uint4*)&g_D[dsel][b][m][0];
#pragma unroll
    for (int j = 0; j < 6; ++j) {
        u32 w[4];
#pragma unroll
        for (int e = 0; e < 4; ++e) {
            __half2 h = __floats2half2_rn(v[j * 8 + 2 * e] * inv, v[j * 8 + 2 * e + 1] * inv);
            w[e] = *reinterpret_cast<u32*>(&h);
        }
        dst[j] = make_uint4(w[0], w[1], w[2], w[3]);
    }
}

// ---------------------------------------------------------------------------
// prep_q: gather query rows (96B copies) + pack exclusion centers.
// ---------------------------------------------------------------------------
__global__ void prep_q(const int* __restrict__ ids, const int* __restrict__ fp2) {
    int g = blockIdx.x * 256 + threadIdx.x;     // dir*32768 + b*2048 + n
    int n = g & (NC_ - 1);
    int b = (g >> 11) & 15;
    int dir = g >> 15;
    int id = ids[b * NC_ + n];
    int fi = fp2[(b * 2 + 0) * NC_ + n];
    int fj = fp2[(b * 2 + 1) * NC_ + n];
    int sel, idx, ci, cj;
    if (dir == 0) { sel = 1; idx = id;             ci = fi;      cj = fj; }
    else          { sel = 0; idx = fi * W_ + fj;   ci = id >> 6; cj = id & 63; }
    const uint4* s = (const uint4*)&g_D[sel][b][idx][0];
    uint4*       d = (uint4*)&g_Q[dir][b][n][0];
#pragma unroll
    for (int k = 0; k < 6; ++k) d[k] = s[k];
    g_ctr[g] = (ci << 8) | cj;
}

// ---------------------------------------------------------------------------
// sort_q: counting sort of queries by center row ci, per (dir,b).
// Intra-bin order is nondeterministic (atomics) but each query's result is
// independent and scattered to its original slot -> output deterministic.
// ---------------------------------------------------------------------------
__global__ void sort_q() {
    __shared__ int hist[64];
    __shared__ int base[64];
    int di = blockIdx.x;                 // dir*B_ + b
    int tid = threadIdx.x;
    if (tid < 64) hist[tid] = 0;
    __syncthreads();
    for (int n = tid; n < NC_; n += 256)
        atomicAdd(&hist[g_ctr[di * NC_ + n] >> 8], 1);
    __syncthreads();
    if (tid == 0) {
        int s = 0;
#pragma unroll
        for (int i = 0; i < 64; ++i) { base[i] = s; s += hist[i]; }
    }
    __syncthreads();
    for (int n = tid; n < NC_; n += 256) {
        int ci = g_ctr[di * NC_ + n] >> 8;
        int pos = atomicAdd(&base[ci], 1);
        g_perm[di * NC_ + pos] = n;
    }
}

// ---------------------------------------------------------------------------
// pair-loop body, templated on whether masking is needed this iter.
// ---------------------------------------------------------------------------
template <bool MASKED>
__device__ __forceinline__ void do_pairs(u32 bbuf, const u32 boff[3],
                                         const u32 a[2][3][4],
                                         const u32 em[2][4], float rmax[4]) {
#pragma unroll
    for (int pair = 0; pair < 8; ++pair) {
        const u32 base0 = bbuf + pair * 2048;
        float d00[4] = {0.f, 0.f, 0.f, 0.f};
        float d01[4] = {0.f, 0.f, 0.f, 0.f};
        float d10[4] = {0.f, 0.f, 0.f, 0.f};
        float d11[4] = {0.f, 0.f, 0.f, 0.f};
#pragma unroll
        for (int ks = 0; ks < 3; ++ks) {
            u32 bb[4];
            ldmx4(bb, base0 + boff[ks]);
            mma16816(d00, a[0][ks], bb + 0);
            mma16816(d01, a[0][ks], bb + 2);
            mma16816(d10, a[1][ks], bb + 0);
            mma16816(d11, a[1][ks], bb + 2);
        }
        if (MASKED) {
            const int h   = pair >> 2;
            const int sh0 = ((pair * 2 + 0) & 7) * 2;
            const int sh1 = ((pair * 2 + 1) & 7) * 2;
            rmax[0] = fold2(rmax[0], d00[0], d00[1], em[h][0], sh0);
            rmax[1] = fold2(rmax[1], d00[2], d00[3], em[h][1], sh0);
            rmax[2] = fold2(rmax[2], d10[0], d10[1], em[h][2], sh0);
            rmax[3] = fold2(rmax[3], d10[2], d10[3], em[h][3], sh0);
            rmax[0] = fold2(rmax[0], d01[0], d01[1], em[h][0], sh1);
            rmax[1] = fold2(rmax[1], d01[2], d01[3], em[h][1], sh1);
            rmax[2] = fold2(rmax[2], d11[0], d11[1], em[h][2], sh1);
            rmax[3] = fold2(rmax[3], d11[2], d11[3], em[h][3], sh1);
        } else {
            rmax[0] = fmaxf(rmax[0], fmaxf(fmaxf(d00[0], d00[1]), fmaxf(d01[0], d01[1])));
            rmax[1] = fmaxf(rmax[1], fmaxf(fmaxf(d00[2], d00[3]), fmaxf(d01[2], d01[3])));
            rmax[2] = fmaxf(rmax[2], fmaxf(fmaxf(d10[0], d10[1]), fmaxf(d11[0], d11[1])));
            rmax[3] = fmaxf(rmax[3], fmaxf(fmaxf(d10[2], d10[3]), fmaxf(d11[2], d11[3])));
        }
    }
}

// ---------------------------------------------------------------------------
// GEMM (mma.sync HMMA) + fused masked-max epilogue, sorted queries.
// grid (16, B_, 2): mt = x>>1 (8 M-tiles of 256 sorted queries), ns = x&1.
// Sorted order makes the row-overlap test warp-coherent -> fast fold ~80%.
// ---------------------------------------------------------------------------
__global__ void __launch_bounds__(256, 2) gemm_kernel() {
    __shared__ __align__(16) char smem[32768];   // B0 @0, B1 @16384
    const u32 sb = s2u(smem);
    const int tid = threadIdx.x;
    const int wq  = tid >> 5;
    const int l   = tid & 31;
    const int lr  = l >> 2;
    const int lc  = l & 3;
    const int mt  = blockIdx.x >> 1;
    const int ns  = blockIdx.x & 1;
    const int b   = blockIdx.y, dir = blockIdx.z;
    const int di  = dir * B_ + b;
    const int qb  = mt * 256 + wq * 32;

    // ---- 4 sorted slots per thread -> original query indices via perm ----
    int qg[4];
    qg[0] = g_perm[di * NC_ + qb + lr];
    qg[1] = g_perm[di * NC_ + qb + lr + 8];
    qg[2] = g_perm[di * NC_ + qb + 16 + lr];
    qg[3] = g_perm[di * NC_ + qb + 16 + lr + 8];
    int ci[4];
    u32 cm[4];
#pragma unroll
    for (int q = 0; q < 4; ++q) {
        int ctr = g_ctr[di * NC_ + qg[q]];
        ci[q] = ctr >> 8;
        int cj = ctr & 255;
        u32 m = 0;
#pragma unroll
        for (int nt7 = 0; nt7 < 8; ++nt7)
#pragma unroll
            for (int cc = 0; cc < 2; ++cc) {
                int col = nt7 * 8 + 2 * lc + cc;
                if (((u32)(col - cj + 4)) <= 8u) m |= 1u << (nt7 * 2 + cc);
            }
        cm[q] = m;
    }

    // ---- A fragments (resident; 2 m-frags x 3 k-steps x 4 regs) ----
    const __half* Qb = &g_Q[dir][b][0][0];
    u32 a[2][3][4];
#pragma unroll
    for (int f = 0; f < 2; ++f)
#pragma unroll
        for (int ks = 0; ks < 3; ++ks) {
            int c0 = ks * 16 + 2 * lc;
            a[f][ks][0] = *(const u32*)&Qb[(size_t)qg[2 * f]     * CC_ + c0];
            a[f][ks][1] = *(const u32*)&Qb[(size_t)qg[2 * f + 1] * CC_ + c0];
            a[f][ks][2] = *(const u32*)&Qb[(size_t)qg[2 * f]     * CC_ + c0 + 8];
            a[f][ks][3] = *(const u32*)&Qb[(size_t)qg[2 * f + 1] * CC_ + c0 + 8];
        }

    // ---- ldmatrix.x4 per-lane B offsets ----
    const int mm  = (l >> 3) & 1;
    const int nto = (l & 16) ? 1024 : 0;
    const int r7  = l & 7;
    u32 boff[3];
#pragma unroll
    for (int ks = 0; ks < 3; ++ks)
        boff[ks] = (u32)(nto + r7 * 128 + (((ks * 2 + mm) ^ r7) << 4));

    const char* gdb = (const char*)&g_D[dir][b][0][0] + (size_t)ns * 16 * 12288;

    // ---- prime stage 0 ----
    {
        int idx = tid;
#pragma unroll
        for (int r = 0; r < 3; ++r, idx += 256) {
            int row = idx / 6, sl = idx % 6;
            cpa16(sb + row * 128 + ((sl ^ (row & 7)) << 4), gdb + idx * 16);
        }
        cpa_commit();
    }

    float rmax[4] = {-1e30f, -1e30f, -1e30f, -1e30f};

    for (int t = 0; t < 16; ++t) {
        if (t < 15) {
            u32 sbuf = sb + (((t + 1) & 1) << 14);
            const char* gsrc = gdb + (size_t)(t + 1) * 12288;
            int idx = tid;
#pragma unroll
            for (int r = 0; r < 3; ++r, idx += 256) {
                int row = idx / 6, sl = idx % 6;
                cpa16(sbuf + row * 128 + ((sl ^ (row & 7)) << 4), gsrc + idx * 16);
            }
            cpa_commit();
            asm volatile("cp.async.wait_group 1;" ::: "memory");
        } else {
            asm volatile("cp.async.wait_group 0;" ::: "memory");
        }
        __syncthreads();

        const u32 bbuf = sb + ((t & 1) << 14);
        const int r0 = (ns * 16 + t) * 2;   // absolute grid row of tile half 0

        // warp-coherent row-overlap test (rows {r0, r0+1} vs [ci-4, ci+4])
        u32 ov = 0;
#pragma unroll
        for (int q = 0; q < 4; ++q)
            ov |= (((u32)(r0 - ci[q] + 5)) <= 9u) ? 1u : 0u;

        if (__any_sync(0xffffffffu, ov)) {
            u32 em[2][4];
#pragma unroll
            for (int q = 0; q < 4; ++q) {
                em[0][q] = (((u32)(r0 + 0 - ci[q] + 4)) <= 8u) ? cm[q] : 0u;
                em[1][q] = (((u32)(r0 + 1 - ci[q] + 4)) <= 8u) ? cm[q] : 0u;
            }
            do_pairs<true>(bbuf, boff, a, em, rmax);
        } else {
            u32 em[2][4];   // unused
            do_pairs<false>(bbuf, boff, a, em, rmax);
        }
        __syncthreads();
    }

    // reduce across the 4 lanes sharing each query row
#pragma unroll
    for (int q = 0; q < 4; ++q) {
        rmax[q] = fmaxf(rmax[q], __shfl_xor_sync(0xffffffffu, rmax[q], 1));
        rmax[q] = fmaxf(rmax[q], __shfl_xor_sync(0xffffffffu, rmax[q], 2));
    }
    if (lc == 0) {
#pragma unroll
        for (int q = 0; q < 4; ++q)
            g_maxdot[ns][di * NC_ + qg[q]] = rmax[q];
    }
}

// ---------------------------------------------------------------------------
// loss_part: grid (16 chunks, B_), block 128. One correspondence per thread.
// ---------------------------------------------------------------------------
__global__ void loss_part(const float* __restrict__ att1,
                          const float* __restrict__ att2,
                          const int* __restrict__ ids,
                          const int* __restrict__ fp2) {
    __shared__ float s_t[128];
    __shared__ float s_w[128];
    int b = blockIdx.y, ch = blockIdx.x, tid = threadIdx.x;
    int n = ch * 128 + tid;

    int id = ids[b * NC_ + n];
    int fi = fp2[(b * 2 + 0) * NC_ + n];
    int fj = fp2[(b * 2 + 1) * NC_ + n];
    int lin = fi * W_ + fj;
    const __half2* qr = (const __half2*)&g_Q[0][b][n][0];
    const __half2* dr = (const __half2*)&g_D[0][b][lin][0];
    float dot = 0.f;
#pragma unroll
    for (int j = 0; j < 24; ++j) {
        float2 a = __half22float2(qr[j]);
        float2 c = __half22float2(dr[j]);
        dot = fmaf(a.x, c.x, dot);
        dot = fmaf(a.y, c.y, dot);
    }
    float mx = fmaxf(fmaxf(g_maxdot[0][b * NC_ + n], g_maxdot[1][b * NC_ + n]),
                     fmaxf(g_maxdot[0][B_ * NC_ + b * NC_ + n],
                           g_maxdot[1][B_ * NC_ + b * NC_ + n]));
    float term = fmaxf(1.0f + 2.0f * (mx - dot), 0.0f);
    float w = att1[b * HW_ + id] * att2[b * HW_ + lin];
    s_t[tid] = w * term;
    s_w[tid] = w;
    __syncthreads();
    for (int s = 64; s > 0; s >>= 1) {
        if (tid < s) { s_t[tid] += s_t[tid + s]; s_w[tid] += s_w[tid + s]; }
        __syncthreads();
    }
    if (tid == 0) { g_pt[b * 16 + ch] = s_t[0]; g_pw[b * 16 + ch] = s_w[0]; }
}

// ---------------------------------------------------------------------------
// loss_final: per-image ratio then batch mean (chunk-ordered, deterministic).
// ---------------------------------------------------------------------------
__global__ void loss_final(float* __restrict__ out) {
    __shared__ float s_l[16];
    int tid = threadIdx.x;
    if (tid < 16) {
        float st = 0.f, sw = 0.f;
#pragma unroll
        for (int c = 0; c < 16; ++c) {
            st += g_pt[tid * 16 + c];
            sw += g_pw[tid * 16 + c];
        }
        s_l[tid] = st / sw;
    }
    __syncwarp();
    if (tid == 0) {
        float s = 0.f;
#pragma unroll
        for (int b = 0; b < B_; ++b) s += s_l[b];
        out[0] = s / (float)B_;
    }
}

// ---------------------------------------------------------------------------
extern "C" void kernel_launch(void* const* d_in, const int* in_sizes, int n_in,
                              void* d_out, int out_size) {
    const float* x1   = (const float*)d_in[0];
    const float* x2   = (const float*)d_in[1];
    const float* att1 = (const float*)d_in[2];
    const float* att2 = (const float*)d_in[3];
    const int*   ids  = (const int*)d_in[4];
    const int*   fp2  = (const int*)d_in[5];
    float* out = (float*)d_out;

    prep_d<<<dim3((B_ * HW_) / 256, 2), 256>>>(x1, x2);
    prep_q<<<(2 * B_ * NC_) / 256, 256>>>(ids, fp2);
    sort_q<<<2 * B_, 256>>>();                    // keeps gemm in ncu slot 4
    gemm_kernel<<<dim3(16, B_, 2), 256>>>();
    loss_part<<<dim3(16, B_), 128>>>(att1, att2, ids, fp2);
    loss_final<<<1, 32>>>(out);
}

// round 15
// speedup vs baseline: 9.7852x; 1.0930x over previous
#include <cuda_runtime.h>
#include <cuda_fp16.h>
#include <math.h>

#define B_   16
#define W_   64
#define HW_  4096
#define NC_  2048
#define CC_  48

typedef unsigned int u32;
typedef unsigned long long u64;

// ---------------- scratch (__device__ globals; no allocation) ----------------
__device__ __half g_D[2][B_][HW_][CC_];   // [0]=norm(x2), [1]=norm(x1); packed 96B rows
__device__ __half g_Q[2][B_][NC_][CC_];   // gathered queries per dir
__device__ int    g_ctr[2 * B_ * NC_];    // (ci<<8)|cj exclusion centers
__device__ int    g_perm[2 * B_ * NC_];   // queries sorted by ci per (dir,b)
__device__ float  g_maxdot[2][2 * B_ * NC_];  // [nsplit][dir*B+b][n]
__device__ float  g_pt[B_ * 16];          // partial weighted-term sums
__device__ float  g_pw[B_ * 16];          // partial weight sums

// ---------------- PTX helpers (portable, no sm_103a-gated features) ---------
__device__ __forceinline__ u32 s2u(const void* p) {
    u32 a;
    asm("{ .reg .u64 t; cvta.to.shared.u64 t, %1; cvt.u32.u64 %0, t; }" : "=r"(a) : "l"(p));
    return a;
}
__device__ __forceinline__ void cpa16(u32 s, const void* g) {
    asm volatile("cp.async.cg.shared.global [%0], [%1], 16;" :: "r"(s), "l"(g) : "memory");
}
__device__ __forceinline__ void cpa_commit() {
    asm volatile("cp.async.commit_group;" ::: "memory");
}
__device__ __forceinline__ void ldmx4(u32* r, u32 addr) {
    asm volatile("ldmatrix.sync.aligned.m8n8.x4.shared.b16 {%0,%1,%2,%3}, [%4];"
                 : "=r"(r[0]), "=r"(r[1]), "=r"(r[2]), "=r"(r[3]) : "r"(addr));
}
__device__ __forceinline__ void mma16816(float* d, const u32* a, const u32* b) {
    asm volatile(
        "mma.sync.aligned.m16n8k16.row.col.f32.f16.f16.f32 "
        "{%0,%1,%2,%3}, {%4,%5,%6,%7}, {%8,%9}, {%0,%1,%2,%3};"
        : "+f"(d[0]), "+f"(d[1]), "+f"(d[2]), "+f"(d[3])
        : "r"(a[0]), "r"(a[1]), "r"(a[2]), "r"(a[3]), "r"(b[0]), "r"(b[1]));
}
__device__ __forceinline__ float fold2(float r, float x, float y, u32 em, int sh) {
    u32 e = em >> sh;
    float vx = (e & 1u) ? -1e30f : x;
    float vy = (e & 2u) ? -1e30f : y;
    return fmaxf(r, fmaxf(vx, vy));
}

// ---------------------------------------------------------------------------
// prep_d: per-pixel L2 normalize -> fp16 packed 96B K-rows.
// ---------------------------------------------------------------------------
__global__ void prep_d(const float* __restrict__ x1, const float* __restrict__ x2) {
    int t = blockIdx.x * 256 + threadIdx.x;
    int b = t >> 12;
    int m = t & (HW_ - 1);
    const float* src = blockIdx.y ? x2 : x1;
    int dsel = blockIdx.y ? 0 : 1;
    const float* p = src + (size_t)b * CC_ * HW_ + m;
    float v[CC_];
    float ss = 0.f;
#pragma unroll
    for (int c = 0; c < CC_; ++c) {
        v[c] = p[c * HW_];
        ss = fmaf(v[c], v[c], ss);
    }
    float inv = 1.0f / fmaxf(sqrtf(ss), 1e-12f);
    uint4* dst = (uint4*)&g_D[dsel][b][m][0];
#pragma unroll
    for (int j = 0; j < 6; ++j) {
        u32 w[4];
#pragma unroll
        for (int e = 0; e < 4; ++e) {
            __half2 h = __floats2half2_rn(v[j * 8 + 2 * e] * inv, v[j * 8 + 2 * e + 1] * inv);
            w[e] = *reinterpret_cast<u32*>(&h);
        }
        dst[j] = make_uint4(w[0], w[1], w[2], w[3]);
    }
}

// ---------------------------------------------------------------------------
// prep_q: gather query rows (96B copies) + pack exclusion centers.
// ---------------------------------------------------------------------------
__global__ void prep_q(const int* __restrict__ ids, const int* __restrict__ fp2) {
    int g = blockIdx.x * 256 + threadIdx.x;     // dir*32768 + b*2048 + n
    int n = g & (NC_ - 1);
    int b = (g >> 11) & 15;
    int dir = g >> 15;
    int id = ids[b * NC_ + n];
    int fi = fp2[(b * 2 + 0) * NC_ + n];
    int fj = fp2[(b * 2 + 1) * NC_ + n];
    int sel, idx, ci, cj;
    if (dir == 0) { sel = 1; idx = id;             ci = fi;      cj = fj; }
    else          { sel = 0; idx = fi * W_ + fj;   ci = id >> 6; cj = id & 63; }
    const uint4* s = (const uint4*)&g_D[sel][b][idx][0];
    uint4*       d = (uint4*)&g_Q[dir][b][n][0];
#pragma unroll
    for (int k = 0; k < 6; ++k) d[k] = s[k];
    g_ctr[g] = (ci << 8) | cj;
}

// ---------------------------------------------------------------------------
// sort_q: counting sort of queries by center row ci, per (dir,b).
// ---------------------------------------------------------------------------
__global__ void sort_q() {
    __shared__ int hist[64];
    __shared__ int base[64];
    int di = blockIdx.x;                 // dir*B_ + b
    int tid = threadIdx.x;
    if (tid < 64) hist[tid] = 0;
    __syncthreads();
    for (int n = tid; n < NC_; n += 256)
        atomicAdd(&hist[g_ctr[di * NC_ + n] >> 8], 1);
    __syncthreads();
    if (tid == 0) {
        int s = 0;
#pragma unroll
        for (int i = 0; i < 64; ++i) { base[i] = s; s += hist[i]; }
    }
    __syncthreads();
    for (int n = tid; n < NC_; n += 256) {
        int ci = g_ctr[di * NC_ + n] >> 8;
        int pos = atomicAdd(&base[ci], 1);
        g_perm[di * NC_ + pos] = n;
    }
}

// ---------------------------------------------------------------------------
// pair-loop body with software-pipelined B fragments.
// ---------------------------------------------------------------------------
template <bool MASKED>
__device__ __forceinline__ void do_pairs(u32 bbuf, const u32 boff[3],
                                         const u32 a[2][3][4],
                                         const u32 em[2][4], float rmax[4]) {
    u32 bcur[3][4], bnxt[3][4];
#pragma unroll
    for (int ks = 0; ks < 3; ++ks) ldmx4(bcur[ks], bbuf + boff[ks]);
#pragma unroll
    for (int pair = 0; pair < 8; ++pair) {
        if (pair < 7) {
            const u32 basen = bbuf + (pair + 1) * 2048;
#pragma unroll
            for (int ks = 0; ks < 3; ++ks) ldmx4(bnxt[ks], basen + boff[ks]);
        }
        float d00[4] = {0.f, 0.f, 0.f, 0.f};
        float d01[4] = {0.f, 0.f, 0.f, 0.f};
        float d10[4] = {0.f, 0.f, 0.f, 0.f};
        float d11[4] = {0.f, 0.f, 0.f, 0.f};
#pragma unroll
        for (int ks = 0; ks < 3; ++ks) {
            mma16816(d00, a[0][ks], bcur[ks] + 0);
            mma16816(d01, a[0][ks], bcur[ks] + 2);
            mma16816(d10, a[1][ks], bcur[ks] + 0);
            mma16816(d11, a[1][ks], bcur[ks] + 2);
        }
        if (MASKED) {
            const int h   = pair >> 2;
            const int sh0 = ((pair * 2 + 0) & 7) * 2;
            const int sh1 = ((pair * 2 + 1) & 7) * 2;
            rmax[0] = fold2(rmax[0], d00[0], d00[1], em[h][0], sh0);
            rmax[1] = fold2(rmax[1], d00[2], d00[3], em[h][1], sh0);
            rmax[2] = fold2(rmax[2], d10[0], d10[1], em[h][2], sh0);
            rmax[3] = fold2(rmax[3], d10[2], d10[3], em[h][3], sh0);
            rmax[0] = fold2(rmax[0], d01[0], d01[1], em[h][0], sh1);
            rmax[1] = fold2(rmax[1], d01[2], d01[3], em[h][1], sh1);
            rmax[2] = fold2(rmax[2], d11[0], d11[1], em[h][2], sh1);
            rmax[3] = fold2(rmax[3], d11[2], d11[3], em[h][3], sh1);
        } else {
            rmax[0] = fmaxf(rmax[0], fmaxf(fmaxf(d00[0], d00[1]), fmaxf(d01[0], d01[1])));
            rmax[1] = fmaxf(rmax[1], fmaxf(fmaxf(d00[2], d00[3]), fmaxf(d01[2], d01[3])));
            rmax[2] = fmaxf(rmax[2], fmaxf(fmaxf(d10[0], d10[1]), fmaxf(d11[0], d11[1])));
            rmax[3] = fmaxf(rmax[3], fmaxf(fmaxf(d10[2], d10[3]), fmaxf(d11[2], d11[3])));
        }
#pragma unroll
        for (int ks = 0; ks < 3; ++ks)
#pragma unroll
            for (int r = 0; r < 4; ++r) bcur[ks][r] = bnxt[ks][r];
    }
}

// ---------------------------------------------------------------------------
// GEMM (mma.sync HMMA) + fused masked-max epilogue, sorted queries.
// grid (32, B_, 2): mt = x>>1 (16 M-tiles of 128 sorted queries), ns = x&1.
// 128 threads = 4 warps -> 4 CTAs/SM (4 barrier domains). 3-stage cp.async
// ring, ONE __syncthreads per iter. 48KB dynamic smem.
// ---------------------------------------------------------------------------
__global__ void __launch_bounds__(128, 4) gemm_kernel() {
    extern __shared__ __align__(16) char smem[];   // 3 stages x 16384
    const u32 sb = s2u(smem);
    const int tid = threadIdx.x;
    const int wq  = tid >> 5;
    const int l   = tid & 31;
    const int lr  = l >> 2;
    const int lc  = l & 3;
    const int mt  = blockIdx.x >> 1;
    const int ns  = blockIdx.x & 1;
    const int b   = blockIdx.y, dir = blockIdx.z;
    const int di  = dir * B_ + b;
    const int qb  = mt * 128 + wq * 32;

    // ---- 4 sorted slots per thread -> original query indices via perm ----
    int qg[4];
    qg[0] = g_perm[di * NC_ + qb + lr];
    qg[1] = g_perm[di * NC_ + qb + lr + 8];
    qg[2] = g_perm[di * NC_ + qb + 16 + lr];
    qg[3] = g_perm[di * NC_ + qb + 16 + lr + 8];
    int ci[4];
    u32 cm[4];
#pragma unroll
    for (int q = 0; q < 4; ++q) {
        int ctr = g_ctr[di * NC_ + qg[q]];
        ci[q] = ctr >> 8;
        int cj = ctr & 255;
        u32 m = 0;
#pragma unroll
        for (int nt7 = 0; nt7 < 8; ++nt7)
#pragma unroll
            for (int cc = 0; cc < 2; ++cc) {
                int col = nt7 * 8 + 2 * lc + cc;
                if (((u32)(col - cj + 4)) <= 8u) m |= 1u << (nt7 * 2 + cc);
            }
        cm[q] = m;
    }

    // ---- A fragments (resident; 2 m-frags x 3 k-steps x 4 regs) ----
    const __half* Qb = &g_Q[dir][b][0][0];
    u32 a[2][3][4];
#pragma unroll
    for (int f = 0; f < 2; ++f)
#pragma unroll
        for (int ks = 0; ks < 3; ++ks) {
            int c0 = ks * 16 + 2 * lc;
            a[f][ks][0] = *(const u32*)&Qb[(size_t)qg[2 * f]     * CC_ + c0];
            a[f][ks][1] = *(const u32*)&Qb[(size_t)qg[2 * f + 1] * CC_ + c0];
            a[f][ks][2] = *(const u32*)&Qb[(size_t)qg[2 * f]     * CC_ + c0 + 8];
            a[f][ks][3] = *(const u32*)&Qb[(size_t)qg[2 * f + 1] * CC_ + c0 + 8];
        }

    // ---- ldmatrix.x4 per-lane B offsets ----
    const int mm  = (l >> 3) & 1;
    const int nto = (l & 16) ? 1024 : 0;
    const int r7  = l & 7;
    u32 boff[3];
#pragma unroll
    for (int ks = 0; ks < 3; ++ks)
        boff[ks] = (u32)(nto + r7 * 128 + (((ks * 2 + mm) ^ r7) << 4));

    const char* gdb = (const char*)&g_D[dir][b][0][0] + (size_t)ns * 16 * 12288;

    // ---- B loader: 6 x 16B chunks per thread (768 total) ----
    auto load_stage = [&](int stage, int t) {
        u32 sbuf = sb + stage * 16384;
        const char* gsrc = gdb + (size_t)t * 12288;
        int idx = tid;
#pragma unroll
        for (int r = 0; r < 6; ++r, idx += 128) {
            int row = idx / 6, sl = idx % 6;
            cpa16(sbuf + row * 128 + ((sl ^ (row & 7)) << 4), gsrc + idx * 16);
        }
    };

    // prime stages 0 and 1
    load_stage(0, 0); cpa_commit();
    load_stage(1, 1); cpa_commit();

    float rmax[4] = {-1e30f, -1e30f, -1e30f, -1e30f};
    int stage = 0;

    for (int t = 0; t < 16; ++t) {
        __syncthreads();                       // all warps done with iter t-1
        if (t + 2 < 16) load_stage((stage + 2) % 3, t + 2);
        cpa_commit();                          // keep group count aligned
        asm volatile("cp.async.wait_group 2;" ::: "memory");   // stage t ready

        const u32 bbuf = sb + stage * 16384;
        const int r0 = (ns * 16 + t) * 2;      // absolute grid row of tile half 0

        u32 ov = 0;
#pragma unroll
        for (int q = 0; q < 4; ++q)
            ov |= (((u32)(r0 - ci[q] + 5)) <= 9u) ? 1u : 0u;

        if (__any_sync(0xffffffffu, ov)) {
            u32 em[2][4];
#pragma unroll
            for (int q = 0; q < 4; ++q) {
                em[0][q] = (((u32)(r0 + 0 - ci[q] + 4)) <= 8u) ? cm[q] : 0u;
                em[1][q] = (((u32)(r0 + 1 - ci[q] + 4)) <= 8u) ? cm[q] : 0u;
            }
            do_pairs<true>(bbuf, boff, a, em, rmax);
        } else {
            u32 em[2][4];   // unused
            do_pairs<false>(bbuf, boff, a, em, rmax);
        }
        stage = (stage + 1) % 3;
    }

    // reduce across the 4 lanes sharing each query row
#pragma unroll
    for (int q = 0; q < 4; ++q) {
        rmax[q] = fmaxf(rmax[q], __shfl_xor_sync(0xffffffffu, rmax[q], 1));
        rmax[q] = fmaxf(rmax[q], __shfl_xor_sync(0xffffffffu, rmax[q], 2));
    }
    if (lc == 0) {
#pragma unroll
        for (int q = 0; q < 4; ++q)
            g_maxdot[ns][di * NC_ + qg[q]] = rmax[q];
    }
}

// ---------------------------------------------------------------------------
// loss_part: grid (16 chunks, B_), block 128. One correspondence per thread.
// ---------------------------------------------------------------------------
__global__ void loss_part(const float* __restrict__ att1,
                          const float* __restrict__ att2,
                          const int* __restrict__ ids,
                          const int* __restrict__ fp2) {
    __shared__ float s_t[128];
    __shared__ float s_w[128];
    int b = blockIdx.y, ch = blockIdx.x, tid = threadIdx.x;
    int n = ch * 128 + tid;

    int id = ids[b * NC_ + n];
    int fi = fp2[(b * 2 + 0) * NC_ + n];
    int fj = fp2[(b * 2 + 1) * NC_ + n];
    int lin = fi * W_ + fj;
    const __half2* qr = (const __half2*)&g_Q[0][b][n][0];
    const __half2* dr = (const __half2*)&g_D[0][b][lin][0];
    float dot = 0.f;
#pragma unroll
    for (int j = 0; j < 24; ++j) {
        float2 a = __half22float2(qr[j]);
        float2 c = __half22float2(dr[j]);
        dot = fmaf(a.x, c.x, dot);
        dot = fmaf(a.y, c.y, dot);
    }
    float mx = fmaxf(fmaxf(g_maxdot[0][b * NC_ + n], g_maxdot[1][b * NC_ + n]),
                     fmaxf(g_maxdot[0][B_ * NC_ + b * NC_ + n],
                           g_maxdot[1][B_ * NC_ + b * NC_ + n]));
    float term = fmaxf(1.0f + 2.0f * (mx - dot), 0.0f);
    float w = att1[b * HW_ + id] * att2[b * HW_ + lin];
    s_t[tid] = w * term;
    s_w[tid] = w;
    __syncthreads();
    for (int s = 64; s > 0; s >>= 1) {
        if (tid < s) { s_t[tid] += s_t[tid + s]; s_w[tid] += s_w[tid + s]; }
        __syncthreads();
    }
    if (tid == 0) { g_pt[b * 16 + ch] = s_t[0]; g_pw[b * 16 + ch] = s_w[0]; }
}

// ---------------------------------------------------------------------------
// loss_final: per-image ratio then batch mean (chunk-ordered, deterministic).
// ---------------------------------------------------------------------------
__global__ void loss_final(float* __restrict__ out) {
    __shared__ float s_l[16];
    int tid = threadIdx.x;
    if (tid < 16) {
        float st = 0.f, sw = 0.f;
#pragma unroll
        for (int c = 0; c < 16; ++c) {
            st += g_pt[tid * 16 + c];
            sw += g_pw[tid * 16 + c];
        }
        s_l[tid] = st / sw;
    }
    __syncwarp();
    if (tid == 0) {
        float s = 0.f;
#pragma unroll
        for (int b = 0; b < B_; ++b) s += s_l[b];
        out[0] = s / (float)B_;
    }
}

// ---------------------------------------------------------------------------
extern "C" void kernel_launch(void* const* d_in, const int* in_sizes, int n_in,
                              void* d_out, int out_size) {
    const float* x1   = (const float*)d_in[0];
    const float* x2   = (const float*)d_in[1];
    const float* att1 = (const float*)d_in[2];
    const float* att2 = (const float*)d_in[3];
    const int*   ids  = (const int*)d_in[4];
    const int*   fp2  = (const int*)d_in[5];
    float* out = (float*)d_out;

    cudaFuncSetAttribute(gemm_kernel, cudaFuncAttributeMaxDynamicSharedMemorySize, 49152);

    prep_d<<<dim3((B_ * HW_) / 256, 2), 256>>>(x1, x2);
    prep_q<<<(2 * B_ * NC_) / 256, 256>>>(ids, fp2);
    sort_q<<<2 * B_, 256>>>();                    // keeps gemm in ncu slot 4
    gemm_kernel<<<dim3(32, B_, 2), 128, 49152>>>();
    loss_part<<<dim3(16, B_), 128>>>(att1, att2, ids, fp2);
    loss_final<<<1, 32>>>(out);
}